// round 8
// baseline (speedup 1.0000x reference)
#include <cuda_runtime.h>
#include <cuda_bf16.h>
#include <cstddef>

// Problem constants
#define B_SZ    16
#define S_SZ    16
#define H_SZ    16
#define HD      64
#define D_MODEL 1024
#define PAST    4096
#define L_TOT   4112
#define M_ROWS  256
#define NSPLIT  4

// Output layout offsets (floats): y | k | v
#define OUT_Y_OFF 0
#define OUT_K_OFF (256*1024)
#define OUT_V_OFF (OUT_K_OFF + 256*4112*64)

// Scratch (device globals; no allocations allowed)
__device__ float g_qkv [M_ROWS * 3 * D_MODEL];     // [256, 3072]
__device__ float g_obuf[M_ROWS * D_MODEL];         // [256, 1024]
__device__ float g_po  [256 * NSPLIT * 16 * 64];
__device__ float g_pm  [256 * NSPLIT * 16];
__device__ float g_pl  [256 * NSPLIT * 16];

// ---- tf32 helpers --------------------------------------------------------
__device__ __forceinline__ unsigned f2tf(float x) {
    unsigned r; asm("cvt.rna.tf32.f32 %0, %1;" : "=r"(r) : "f"(x)); return r;
}
__device__ __forceinline__ void tf_split(float x, unsigned& hi, unsigned& lo) {
    hi = f2tf(x);
    lo = f2tf(x - __uint_as_float(hi));
}
__device__ __forceinline__ void mma_tf32(float& c0, float& c1, float& c2, float& c3,
                                         unsigned a0, unsigned a1, unsigned a2, unsigned a3,
                                         unsigned b0, unsigned b1) {
    asm volatile(
        "mma.sync.aligned.m16n8k8.row.col.f32.tf32.tf32.f32 "
        "{%0,%1,%2,%3}, {%4,%5,%6,%7}, {%8,%9}, {%0,%1,%2,%3};\n"
        : "+f"(c0), "+f"(c1), "+f"(c2), "+f"(c3)
        : "r"(a0), "r"(a1), "r"(a2), "r"(a3), "r"(b0), "r"(b1));
}

// ---------------------------------------------------------------------------
// Tensor-core GEMM (3xTF32): C[M,N] = A[M,K] @ W[N,K]^T + bias[N]
// 64x64 block tile, 256 threads (8 warps). Warp w: m-frag = w>>1 (16 rows),
// n-half = w&1 (32 cols = 4 n-frags). A/W hi/lo split at staging.
// smem stride 72 -> bank = 8k+m (mod 32): conflict-free staging + frag loads.
// ---------------------------------------------------------------------------
__global__ __launch_bounds__(256)
void gemm_tf32_kernel(const float* __restrict__ A, const float* __restrict__ W,
                      const float* __restrict__ bias, float* __restrict__ C,
                      int N, int K) {
    __shared__ unsigned Ah[16][72], Al[16][72];
    __shared__ unsigned Bh[16][72], Bl[16][72];

    const int tid = threadIdx.x;
    const int w   = tid >> 5;
    const int L   = tid & 31;
    const int lr4 = L >> 2;           // 0..7
    const int lc4 = L & 3;            // 0..3
    const int mf  = w >> 1;           // m-frag 0..3
    const int nh  = w & 1;            // n-half 0..1

    const int m0 = blockIdx.y * 64;
    const int n0 = blockIdx.x * 64;
    const int lr = tid >> 2;          // staging row 0..63
    const int lk = (tid & 3) * 4;     // staging k offset 0,4,8,12

    float acc[4][4];
    #pragma unroll
    for (int i = 0; i < 4; i++)
        #pragma unroll
        for (int j = 0; j < 4; j++) acc[i][j] = 0.f;

    const int mbase = mf * 16;
    const int nbase = nh * 32;

    for (int k0 = 0; k0 < K; k0 += 16) {
        float4 a4 = *(const float4*)&A[(size_t)(m0 + lr) * K + k0 + lk];
        float4 b4 = *(const float4*)&W[(size_t)(n0 + lr) * K + k0 + lk];
        __syncthreads();     // previous iteration's fragments consumed

        unsigned hi, lo;
        tf_split(a4.x, hi, lo); Ah[lk + 0][lr] = hi; Al[lk + 0][lr] = lo;
        tf_split(a4.y, hi, lo); Ah[lk + 1][lr] = hi; Al[lk + 1][lr] = lo;
        tf_split(a4.z, hi, lo); Ah[lk + 2][lr] = hi; Al[lk + 2][lr] = lo;
        tf_split(a4.w, hi, lo); Ah[lk + 3][lr] = hi; Al[lk + 3][lr] = lo;
        tf_split(b4.x, hi, lo); Bh[lk + 0][lr] = hi; Bl[lk + 0][lr] = lo;
        tf_split(b4.y, hi, lo); Bh[lk + 1][lr] = hi; Bl[lk + 1][lr] = lo;
        tf_split(b4.z, hi, lo); Bh[lk + 2][lr] = hi; Bl[lk + 2][lr] = lo;
        tf_split(b4.w, hi, lo); Bh[lk + 3][lr] = hi; Bl[lk + 3][lr] = lo;
        __syncthreads();

        #pragma unroll
        for (int ks = 0; ks < 2; ks++) {
            const int kk = ks * 8;
            // A fragment (row-major m16 x k8)
            unsigned ah0 = Ah[kk + lc4    ][mbase + lr4    ];
            unsigned ah1 = Ah[kk + lc4    ][mbase + lr4 + 8];
            unsigned ah2 = Ah[kk + 4 + lc4][mbase + lr4    ];
            unsigned ah3 = Ah[kk + 4 + lc4][mbase + lr4 + 8];
            unsigned al0 = Al[kk + lc4    ][mbase + lr4    ];
            unsigned al1 = Al[kk + lc4    ][mbase + lr4 + 8];
            unsigned al2 = Al[kk + 4 + lc4][mbase + lr4    ];
            unsigned al3 = Al[kk + 4 + lc4][mbase + lr4 + 8];

            #pragma unroll
            for (int nf = 0; nf < 4; nf++) {
                const int nn = nbase + nf * 8 + lr4;
                unsigned bh0 = Bh[kk + lc4    ][nn];
                unsigned bh1 = Bh[kk + 4 + lc4][nn];
                unsigned bl0 = Bl[kk + lc4    ][nn];
                unsigned bl1 = Bl[kk + 4 + lc4][nn];
                mma_tf32(acc[nf][0], acc[nf][1], acc[nf][2], acc[nf][3],
                         ah0, ah1, ah2, ah3, bh0, bh1);
                mma_tf32(acc[nf][0], acc[nf][1], acc[nf][2], acc[nf][3],
                         ah0, ah1, ah2, ah3, bl0, bl1);
                mma_tf32(acc[nf][0], acc[nf][1], acc[nf][2], acc[nf][3],
                         al0, al1, al2, al3, bh0, bh1);
            }
        }
    }

    // epilogue: C frag c0 (m=lr4, n=lc4*2), c1 n+1, c2/c3 m+8; add bias
    const int row0 = m0 + mbase + lr4;
    #pragma unroll
    for (int nf = 0; nf < 4; nf++) {
        const int n = n0 + nbase + nf * 8 + lc4 * 2;
        float2 bb = *(const float2*)&bias[n];
        *(float2*)&C[(size_t)row0 * N + n] =
            make_float2(acc[nf][0] + bb.x, acc[nf][1] + bb.y);
        *(float2*)&C[(size_t)(row0 + 8) * N + n] =
            make_float2(acc[nf][2] + bb.x, acc[nf][3] + bb.y);
    }
}

// ---------------------------------------------------------------------------
// Scatter freshly projected K/V rows into positions [4096, 4112).
// ---------------------------------------------------------------------------
__global__ __launch_bounds__(256)
void scatter_newkv_kernel(float* __restrict__ Kd, float* __restrict__ Vd) {
    const unsigned i = blockIdx.x * 256u + threadIdx.x;    // < 65536
    const unsigned c = i & 15u;
    const unsigned s = (i >> 4) & 15u;
    const unsigned h = (i >> 8) & 15u;
    const unsigned b = i >> 12;
    const size_t qoff = (size_t)(b * 16 + s) * 3072 + h * 64 + c * 4;
    const size_t doff = ((size_t)(b * 16 + h) * L_TOT + PAST + s) * 64 + c * 4;
    *(float4*)&Kd[doff] = *(const float4*)&g_qkv[qoff + 1024];
    *(float4*)&Vd[doff] = *(const float4*)&g_qkv[qoff + 2048];
}

// ---------------------------------------------------------------------------
// Fused attention + cache copy-out, split-KV x4, 3xTF32 tensor cores.
// (unchanged from round 7)
// ---------------------------------------------------------------------------
__global__ __launch_bounds__(256)
void attn_split_kernel(const float* __restrict__ cache_k,
                       const float* __restrict__ cache_v,
                       float* __restrict__ out_k,
                       float* __restrict__ out_v) {
    __shared__ unsigned qh[16][68];    // q hi (tf32 bits)
    __shared__ unsigned ql[16][68];    // q lo
    __shared__ float kt[64][68];
    __shared__ float vt[64][68];
    __shared__ float ptT[16][68];
    __shared__ float m_run[16], l_run[16], fac_s[16];

    const int tid   = threadIdx.x;
    const int bh    = blockIdx.x >> 2;
    const int split = blockIdx.x & 3;
    const int b = bh >> 4, h = bh & 15;

    const int w  = tid >> 5;          // warp 0..7
    const int L  = tid & 31;          // lane
    const int lr4 = L >> 2;           // 0..7
    const int lc4 = L & 3;            // 0..3

    // ---- load q, scale by 1/8, split hi/lo into smem ----
    {
        const int q = tid >> 4, c4 = tid & 15;
        float4 qv = *(const float4*)&g_qkv[(size_t)(b * 16 + q) * 3072 + h * 64 + c4 * 4];
        qv.x *= 0.125f; qv.y *= 0.125f; qv.z *= 0.125f; qv.w *= 0.125f;
        unsigned hi, lo;
        tf_split(qv.x, hi, lo); qh[q][c4 * 4 + 0] = hi; ql[q][c4 * 4 + 0] = lo;
        tf_split(qv.y, hi, lo); qh[q][c4 * 4 + 1] = hi; ql[q][c4 * 4 + 1] = lo;
        tf_split(qv.z, hi, lo); qh[q][c4 * 4 + 2] = hi; ql[q][c4 * 4 + 2] = lo;
        tf_split(qv.w, hi, lo); qh[q][c4 * 4 + 3] = hi; ql[q][c4 * 4 + 3] = lo;
    }
    if (tid < 16) { m_run[tid] = -1e30f; l_run[tid] = 0.0f; }

    const int chunk0 = split * 1024;
    const int nrows  = (split == 3) ? 1040 : 1024;
    const int ntiles = (split == 3) ? 17 : 16;
    const size_t cbase = (size_t)bh * (PAST * 64);
    const size_t obase = (size_t)bh * (L_TOT * 64);

    // softmax mapping
    const int pq = tid >> 4;           // query 0..15
    const int dc = tid & 15;           // 4-score segment

    // O fragment (dims w*8 + lc4*2, +1 ; rows lr4, lr4+8)
    float oc0 = 0.f, oc1 = 0.f, oc2 = 0.f, oc3 = 0.f;

    for (int t = 0; t < ntiles; t++) {
        const int l0   = chunk0 + t * 64;
        const int rows = min(64, chunk0 + nrows - l0);   // 64 or 16
        __syncthreads();   // previous tile fully consumed

        // ---- stage K/V tile (fused copy-out for cache rows) ----
        #pragma unroll
        for (int i = 0; i < 4; i++) {
            int idx = i * 256 + tid;
            int r = idx >> 4, c = idx & 15;
            if (r < rows) {
                int gl = l0 + r;
                float4 k4, v4;
                if (gl < PAST) {
                    k4 = *(const float4*)&cache_k[cbase + (size_t)gl * 64 + c * 4];
                    v4 = *(const float4*)&cache_v[cbase + (size_t)gl * 64 + c * 4];
                    *(float4*)&out_k[obase + (size_t)gl * 64 + c * 4] = k4;
                    *(float4*)&out_v[obase + (size_t)gl * 64 + c * 4] = v4;
                } else {
                    k4 = *(const float4*)&out_k[obase + (size_t)gl * 64 + c * 4];
                    v4 = *(const float4*)&out_v[obase + (size_t)gl * 64 + c * 4];
                }
                *(float4*)&kt[r][c * 4] = k4;
                *(float4*)&vt[r][c * 4] = v4;
            }
        }
        __syncthreads();

        // ---- scores via 3xTF32 mma: warp w -> KV rows w*8..w*8+7 ----
        {
            float c0 = 0.f, c1 = 0.f, c2 = 0.f, c3 = 0.f;
            #pragma unroll
            for (int ks = 0; ks < 8; ks++) {
                const int k0 = ks * 8;
                unsigned ah0 = qh[lr4    ][k0 + lc4];
                unsigned ah1 = qh[lr4 + 8][k0 + lc4];
                unsigned ah2 = qh[lr4    ][k0 + 4 + lc4];
                unsigned ah3 = qh[lr4 + 8][k0 + 4 + lc4];
                unsigned al0 = ql[lr4    ][k0 + lc4];
                unsigned al1 = ql[lr4 + 8][k0 + lc4];
                unsigned al2 = ql[lr4    ][k0 + 4 + lc4];
                unsigned al3 = ql[lr4 + 8][k0 + 4 + lc4];
                float b0f = kt[w * 8 + lr4][k0 + lc4];
                float b1f = kt[w * 8 + lr4][k0 + 4 + lc4];
                unsigned bh0, bl0, bh1, bl1;
                tf_split(b0f, bh0, bl0);
                tf_split(b1f, bh1, bl1);
                mma_tf32(c0, c1, c2, c3, ah0, ah1, ah2, ah3, bh0, bh1);
                mma_tf32(c0, c1, c2, c3, ah0, ah1, ah2, ah3, bl0, bl1);
                mma_tf32(c0, c1, c2, c3, al0, al1, al2, al3, bh0, bh1);
            }
            const int n = w * 8 + lc4 * 2;
            ptT[lr4    ][n    ] = (n     < rows) ? c0 : -1e30f;
            ptT[lr4    ][n + 1] = (n + 1 < rows) ? c1 : -1e30f;
            ptT[lr4 + 8][n    ] = (n     < rows) ? c2 : -1e30f;
            ptT[lr4 + 8][n + 1] = (n + 1 < rows) ? c3 : -1e30f;
        }
        __syncthreads();

        // ---- softmax partial: thread = (q=pq, seg=dc) over 4 scores ----
        {
            float4 p = *(const float4*)&ptT[pq][dc * 4];
            float mt = fmaxf(fmaxf(p.x, p.y), fmaxf(p.z, p.w));
            #pragma unroll
            for (int s = 8; s >= 1; s >>= 1)
                mt = fmaxf(mt, __shfl_xor_sync(0xffffffffu, mt, s, 16));
            const float mo = m_run[pq];
            const float mn = fmaxf(mo, mt);
            const float fc = __expf(mo - mn);
            p.x = __expf(p.x - mn); p.y = __expf(p.y - mn);
            p.z = __expf(p.z - mn); p.w = __expf(p.w - mn);
            *(float4*)&ptT[pq][dc * 4] = p;
            float ss = p.x + p.y + p.z + p.w;
            #pragma unroll
            for (int s = 8; s >= 1; s >>= 1)
                ss += __shfl_xor_sync(0xffffffffu, ss, s, 16);
            if (dc == 0) {
                m_run[pq] = mn;
                fac_s[pq] = fc;
                l_run[pq] = l_run[pq] * fc + ss;
            }
        }
        __syncthreads();

        // ---- AV via 3xTF32 mma: warp w -> output dims w*8..w*8+7 ----
        {
            const float f0 = fac_s[lr4];
            const float f1 = fac_s[lr4 + 8];
            oc0 *= f0; oc1 *= f0; oc2 *= f1; oc3 *= f1;

            #pragma unroll
            for (int ks = 0; ks < 8; ks++) {
                const int k0 = ks * 8;
                float af0 = ptT[lr4    ][k0 + lc4];
                float af1 = ptT[lr4 + 8][k0 + lc4];
                float af2 = ptT[lr4    ][k0 + 4 + lc4];
                float af3 = ptT[lr4 + 8][k0 + 4 + lc4];
                unsigned ah0, al0, ah1, al1, ah2, al2, ah3, al3;
                tf_split(af0, ah0, al0);
                tf_split(af1, ah1, al1);
                tf_split(af2, ah2, al2);
                tf_split(af3, ah3, al3);
                float b0f = vt[k0 + lc4    ][w * 8 + lr4];
                float b1f = vt[k0 + 4 + lc4][w * 8 + lr4];
                unsigned bh0, bl0, bh1, bl1;
                tf_split(b0f, bh0, bl0);
                tf_split(b1f, bh1, bl1);
                mma_tf32(oc0, oc1, oc2, oc3, ah0, ah1, ah2, ah3, bh0, bh1);
                mma_tf32(oc0, oc1, oc2, oc3, ah0, ah1, ah2, ah3, bl0, bl1);
                mma_tf32(oc0, oc1, oc2, oc3, al0, al1, al2, al3, bh0, bh1);
            }
        }
    }

    // ---- write partials ----
    {
        const size_t pbase = (size_t)blockIdx.x * 1024;
        const int d = w * 8 + lc4 * 2;
        *(float2*)&g_po[pbase + lr4       * 64 + d] = make_float2(oc0, oc1);
        *(float2*)&g_po[pbase + (lr4 + 8) * 64 + d] = make_float2(oc2, oc3);
    }
    if (tid < 16) {
        g_pm[blockIdx.x * 16 + tid] = m_run[tid];
        g_pl[blockIdx.x * 16 + tid] = l_run[tid];
    }
}

// ---------------------------------------------------------------------------
// Combine split partials -> g_obuf [B,S,H*hd]
// ---------------------------------------------------------------------------
__global__ __launch_bounds__(256)
void attn_reduce_kernel() {
    const int bh = blockIdx.x;
    const int tid = threadIdx.x;
    const int pq = tid >> 4, dc = tid & 15;
    const int base = bh * NSPLIT;

    float mm = -1e30f;
    #pragma unroll
    for (int s = 0; s < NSPLIT; s++)
        mm = fmaxf(mm, g_pm[(base + s) * 16 + pq]);

    float4 acc = make_float4(0.f, 0.f, 0.f, 0.f);
    float l = 0.f;
    #pragma unroll
    for (int s = 0; s < NSPLIT; s++) {
        float w = __expf(g_pm[(base + s) * 16 + pq] - mm);
        float4 o = *(const float4*)&g_po[(size_t)(base + s) * 1024 + pq * 64 + dc * 4];
        acc.x += w * o.x; acc.y += w * o.y;
        acc.z += w * o.z; acc.w += w * o.w;
        l += w * g_pl[(base + s) * 16 + pq];
    }
    float inv = 1.0f / l;
    const int b = bh >> 4, h = bh & 15;
    float4 r = make_float4(acc.x * inv, acc.y * inv, acc.z * inv, acc.w * inv);
    *(float4*)&g_obuf[(size_t)(b * 16 + pq) * D_MODEL + h * 64 + dc * 4] = r;
}

// ---------------------------------------------------------------------------
extern "C" void kernel_launch(void* const* d_in, const int* in_sizes, int n_in,
                              void* d_out, int out_size) {
    const float* x       = (const float*)d_in[0];
    const float* cache_k = (const float*)d_in[1];
    const float* cache_v = (const float*)d_in[2];
    const float* qkv_w   = (const float*)d_in[3];
    const float* qkv_b   = (const float*)d_in[4];
    const float* out_w   = (const float*)d_in[5];
    const float* out_b   = (const float*)d_in[6];

    float* out   = (float*)d_out;
    float* out_y = out + OUT_Y_OFF;
    float* out_k = out + OUT_K_OFF;
    float* out_v = out + OUT_V_OFF;

    float *qkv_p = nullptr, *obuf_p = nullptr;
    cudaGetSymbolAddress((void**)&qkv_p,  g_qkv);
    cudaGetSymbolAddress((void**)&obuf_p, g_obuf);

    // 1) QKV projection -> g_qkv [256,3072]  (3xTF32 tensor cores)
    gemm_tf32_kernel<<<dim3(3072 / 64, M_ROWS / 64), 256>>>(
        x, qkv_w, qkv_b, qkv_p, 3072, D_MODEL);

    // 2) Append new K/V rows into out_k/out_v tails
    scatter_newkv_kernel<<<256, 256>>>(out_k, out_v);

    // 3) Fused attention + cache copy-out (split-KV x4, 3xTF32 tensor cores)
    attn_split_kernel<<<B_SZ * H_SZ * NSPLIT, 256>>>(cache_k, cache_v, out_k, out_v);

    // 4) Combine splits -> g_obuf
    attn_reduce_kernel<<<B_SZ * H_SZ, 256>>>();

    // 5) Output projection -> y  (3xTF32 tensor cores)
    gemm_tf32_kernel<<<dim3(D_MODEL / 64, M_ROWS / 64), 256>>>(
        obuf_p, out_w, out_b, out_y, D_MODEL, D_MODEL);
}

// round 9
// speedup vs baseline: 1.1359x; 1.1359x over previous
#include <cuda_runtime.h>
#include <cuda_bf16.h>
#include <cstddef>

// Problem constants
#define B_SZ    16
#define S_SZ    16
#define H_SZ    16
#define HD      64
#define D_MODEL 1024
#define PAST    4096
#define L_TOT   4112
#define M_ROWS  256
#define NSPLIT  4

// Output layout offsets (floats): y | k | v
#define OUT_Y_OFF 0
#define OUT_K_OFF (256*1024)
#define OUT_V_OFF (OUT_K_OFF + 256*4112*64)

// cp.async helpers
__device__ __forceinline__ unsigned smem_u32(const void* p) {
    return (unsigned)__cvta_generic_to_shared(p);
}
#define CP_ASYNC16(dst_u32, src_ptr) \
    asm volatile("cp.async.cg.shared.global [%0], [%1], 16;\n" \
                 :: "r"(dst_u32), "l"(src_ptr))
#define CP_COMMIT() asm volatile("cp.async.commit_group;\n" ::)
#define CP_WAIT1()  asm volatile("cp.async.wait_group 1;\n" ::)
#define CP_WAIT0()  asm volatile("cp.async.wait_group 0;\n" ::)

// Scratch (device globals; no allocations allowed)
__device__ float g_qkv [M_ROWS * 3 * D_MODEL];     // [256, 3072]
__device__ float g_obuf[M_ROWS * D_MODEL];         // [256, 1024]
__device__ float g_po  [256 * NSPLIT * 16 * 64];
__device__ float g_pm  [256 * NSPLIT * 16];
__device__ float g_pl  [256 * NSPLIT * 16];

// ---- tf32 helpers --------------------------------------------------------
__device__ __forceinline__ unsigned f2tf(float x) {
    unsigned r; asm("cvt.rna.tf32.f32 %0, %1;" : "=r"(r) : "f"(x)); return r;
}
__device__ __forceinline__ void tf_split(float x, unsigned& hi, unsigned& lo) {
    hi = f2tf(x);
    lo = f2tf(x - __uint_as_float(hi));
}
__device__ __forceinline__ void mma_tf32(float& c0, float& c1, float& c2, float& c3,
                                         unsigned a0, unsigned a1, unsigned a2, unsigned a3,
                                         unsigned b0, unsigned b1) {
    asm volatile(
        "mma.sync.aligned.m16n8k8.row.col.f32.tf32.tf32.f32 "
        "{%0,%1,%2,%3}, {%4,%5,%6,%7}, {%8,%9}, {%0,%1,%2,%3};\n"
        : "+f"(c0), "+f"(c1), "+f"(c2), "+f"(c3)
        : "r"(a0), "r"(a1), "r"(a2), "r"(a3), "r"(b0), "r"(b1));
}

// ---------------------------------------------------------------------------
// Tensor-core GEMM (3xTF32) with cp.async double-buffered staging.
// C[M,N] = A[M,K] @ W[N,K]^T + bias[N]. 64x64 tile, 256 threads (8 warps).
// Raw fp32 tiles in smem (row stride 20 floats = 80B: 16B-aligned for
// cp.async; bank = (20m+k)%32 conflict-free for frag loads). hi/lo split
// happens at fragment-load time.
// ---------------------------------------------------------------------------
__global__ __launch_bounds__(256)
void gemm_tf32_kernel(const float* __restrict__ A, const float* __restrict__ W,
                      const float* __restrict__ bias, float* __restrict__ C,
                      int N, int K) {
    __shared__ __align__(16) float As[2][64][20];
    __shared__ __align__(16) float Bs[2][64][20];

    const int tid = threadIdx.x;
    const int w   = tid >> 5;
    const int L   = tid & 31;
    const int lr4 = L >> 2;           // 0..7
    const int lc4 = L & 3;            // 0..3
    const int mf  = w >> 1;           // m-frag 0..3
    const int nh  = w & 1;            // n-half 0..1

    const int m0 = blockIdx.y * 64;
    const int n0 = blockIdx.x * 64;

    // staging mapping: 1 x 16B chunk per thread per tensor
    const int srow = tid >> 2;        // 0..63
    const int sch  = (tid & 3) * 4;   // k offset 0,4,8,12

    float acc[4][4];
    #pragma unroll
    for (int i = 0; i < 4; i++)
        #pragma unroll
        for (int j = 0; j < 4; j++) acc[i][j] = 0.f;

    const int mbase = mf * 16;
    const int nbase = nh * 32;
    const int niter = K / 16;

    // prologue: stage k-slab 0 into buffer 0
    CP_ASYNC16(smem_u32(&As[0][srow][sch]), &A[(size_t)(m0 + srow) * K + sch]);
    CP_ASYNC16(smem_u32(&Bs[0][srow][sch]), &W[(size_t)(n0 + srow) * K + sch]);
    CP_COMMIT();

    for (int t = 0; t < niter; t++) {
        const int bb = t & 1;

        if (t + 1 < niter) {
            const int k1 = (t + 1) * 16;
            CP_ASYNC16(smem_u32(&As[bb ^ 1][srow][sch]),
                       &A[(size_t)(m0 + srow) * K + k1 + sch]);
            CP_ASYNC16(smem_u32(&Bs[bb ^ 1][srow][sch]),
                       &W[(size_t)(n0 + srow) * K + k1 + sch]);
            CP_COMMIT();
            CP_WAIT1();      // slab t complete; t+1 in flight
        } else {
            CP_WAIT0();
        }
        __syncthreads();     // staged slab visible to all

        #pragma unroll
        for (int ks = 0; ks < 2; ks++) {
            const int kk = ks * 8;
            // A fragment (row-major m16 x k8), split hi/lo on the fly
            float af0 = As[bb][mbase + lr4    ][kk + lc4];
            float af1 = As[bb][mbase + lr4 + 8][kk + lc4];
            float af2 = As[bb][mbase + lr4    ][kk + 4 + lc4];
            float af3 = As[bb][mbase + lr4 + 8][kk + 4 + lc4];
            unsigned ah0, al0, ah1, al1, ah2, al2, ah3, al3;
            tf_split(af0, ah0, al0);
            tf_split(af1, ah1, al1);
            tf_split(af2, ah2, al2);
            tf_split(af3, ah3, al3);

            #pragma unroll
            for (int nf = 0; nf < 4; nf++) {
                const int nn = nbase + nf * 8 + lr4;
                float bf0 = Bs[bb][nn][kk + lc4];
                float bf1 = Bs[bb][nn][kk + 4 + lc4];
                unsigned bh0, bl0, bh1, bl1;
                tf_split(bf0, bh0, bl0);
                tf_split(bf1, bh1, bl1);
                mma_tf32(acc[nf][0], acc[nf][1], acc[nf][2], acc[nf][3],
                         ah0, ah1, ah2, ah3, bh0, bh1);
                mma_tf32(acc[nf][0], acc[nf][1], acc[nf][2], acc[nf][3],
                         ah0, ah1, ah2, ah3, bl0, bl1);
                mma_tf32(acc[nf][0], acc[nf][1], acc[nf][2], acc[nf][3],
                         al0, al1, al2, al3, bh0, bh1);
            }
        }
        __syncthreads();     // slab consumed; next cp.async may overwrite
    }

    // epilogue: C frag c0 (m=lr4, n=lc4*2), c1 n+1, c2/c3 m+8; add bias
    const int row0 = m0 + mbase + lr4;
    #pragma unroll
    for (int nf = 0; nf < 4; nf++) {
        const int n = n0 + nbase + nf * 8 + lc4 * 2;
        float2 bb2 = *(const float2*)&bias[n];
        *(float2*)&C[(size_t)row0 * N + n] =
            make_float2(acc[nf][0] + bb2.x, acc[nf][1] + bb2.y);
        *(float2*)&C[(size_t)(row0 + 8) * N + n] =
            make_float2(acc[nf][2] + bb2.x, acc[nf][3] + bb2.y);
    }
}

// ---------------------------------------------------------------------------
// Scatter freshly projected K/V rows into positions [4096, 4112).
// ---------------------------------------------------------------------------
__global__ __launch_bounds__(256)
void scatter_newkv_kernel(float* __restrict__ Kd, float* __restrict__ Vd) {
    const unsigned i = blockIdx.x * 256u + threadIdx.x;    // < 65536
    const unsigned c = i & 15u;
    const unsigned s = (i >> 4) & 15u;
    const unsigned h = (i >> 8) & 15u;
    const unsigned b = i >> 12;
    const size_t qoff = (size_t)(b * 16 + s) * 3072 + h * 64 + c * 4;
    const size_t doff = ((size_t)(b * 16 + h) * L_TOT + PAST + s) * 64 + c * 4;
    *(float4*)&Kd[doff] = *(const float4*)&g_qkv[qoff + 1024];
    *(float4*)&Vd[doff] = *(const float4*)&g_qkv[qoff + 2048];
}

// ---------------------------------------------------------------------------
// Fused attention + cache copy-out, split-KV x4, 3xTF32 tensor cores.
// (unchanged from round 7)
// ---------------------------------------------------------------------------
__global__ __launch_bounds__(256)
void attn_split_kernel(const float* __restrict__ cache_k,
                       const float* __restrict__ cache_v,
                       float* __restrict__ out_k,
                       float* __restrict__ out_v) {
    __shared__ unsigned qh[16][68];    // q hi (tf32 bits)
    __shared__ unsigned ql[16][68];    // q lo
    __shared__ float kt[64][68];
    __shared__ float vt[64][68];
    __shared__ float ptT[16][68];
    __shared__ float m_run[16], l_run[16], fac_s[16];

    const int tid   = threadIdx.x;
    const int bh    = blockIdx.x >> 2;
    const int split = blockIdx.x & 3;
    const int b = bh >> 4, h = bh & 15;

    const int w  = tid >> 5;          // warp 0..7
    const int L  = tid & 31;          // lane
    const int lr4 = L >> 2;           // 0..7
    const int lc4 = L & 3;            // 0..3

    // ---- load q, scale by 1/8, split hi/lo into smem ----
    {
        const int q = tid >> 4, c4 = tid & 15;
        float4 qv = *(const float4*)&g_qkv[(size_t)(b * 16 + q) * 3072 + h * 64 + c4 * 4];
        qv.x *= 0.125f; qv.y *= 0.125f; qv.z *= 0.125f; qv.w *= 0.125f;
        unsigned hi, lo;
        tf_split(qv.x, hi, lo); qh[q][c4 * 4 + 0] = hi; ql[q][c4 * 4 + 0] = lo;
        tf_split(qv.y, hi, lo); qh[q][c4 * 4 + 1] = hi; ql[q][c4 * 4 + 1] = lo;
        tf_split(qv.z, hi, lo); qh[q][c4 * 4 + 2] = hi; ql[q][c4 * 4 + 2] = lo;
        tf_split(qv.w, hi, lo); qh[q][c4 * 4 + 3] = hi; ql[q][c4 * 4 + 3] = lo;
    }
    if (tid < 16) { m_run[tid] = -1e30f; l_run[tid] = 0.0f; }

    const int chunk0 = split * 1024;
    const int nrows  = (split == 3) ? 1040 : 1024;
    const int ntiles = (split == 3) ? 17 : 16;
    const size_t cbase = (size_t)bh * (PAST * 64);
    const size_t obase = (size_t)bh * (L_TOT * 64);

    // softmax mapping
    const int pq = tid >> 4;           // query 0..15
    const int dc = tid & 15;           // 4-score segment

    // O fragment (dims w*8 + lc4*2, +1 ; rows lr4, lr4+8)
    float oc0 = 0.f, oc1 = 0.f, oc2 = 0.f, oc3 = 0.f;

    for (int t = 0; t < ntiles; t++) {
        const int l0   = chunk0 + t * 64;
        const int rows = min(64, chunk0 + nrows - l0);   // 64 or 16
        __syncthreads();   // previous tile fully consumed

        // ---- stage K/V tile (fused copy-out for cache rows) ----
        #pragma unroll
        for (int i = 0; i < 4; i++) {
            int idx = i * 256 + tid;
            int r = idx >> 4, c = idx & 15;
            if (r < rows) {
                int gl = l0 + r;
                float4 k4, v4;
                if (gl < PAST) {
                    k4 = *(const float4*)&cache_k[cbase + (size_t)gl * 64 + c * 4];
                    v4 = *(const float4*)&cache_v[cbase + (size_t)gl * 64 + c * 4];
                    *(float4*)&out_k[obase + (size_t)gl * 64 + c * 4] = k4;
                    *(float4*)&out_v[obase + (size_t)gl * 64 + c * 4] = v4;
                } else {
                    k4 = *(const float4*)&out_k[obase + (size_t)gl * 64 + c * 4];
                    v4 = *(const float4*)&out_v[obase + (size_t)gl * 64 + c * 4];
                }
                *(float4*)&kt[r][c * 4] = k4;
                *(float4*)&vt[r][c * 4] = v4;
            }
        }
        __syncthreads();

        // ---- scores via 3xTF32 mma: warp w -> KV rows w*8..w*8+7 ----
        {
            float c0 = 0.f, c1 = 0.f, c2 = 0.f, c3 = 0.f;
            #pragma unroll
            for (int ks = 0; ks < 8; ks++) {
                const int k0 = ks * 8;
                unsigned ah0 = qh[lr4    ][k0 + lc4];
                unsigned ah1 = qh[lr4 + 8][k0 + lc4];
                unsigned ah2 = qh[lr4    ][k0 + 4 + lc4];
                unsigned ah3 = qh[lr4 + 8][k0 + 4 + lc4];
                unsigned al0 = ql[lr4    ][k0 + lc4];
                unsigned al1 = ql[lr4 + 8][k0 + lc4];
                unsigned al2 = ql[lr4    ][k0 + 4 + lc4];
                unsigned al3 = ql[lr4 + 8][k0 + 4 + lc4];
                float b0f = kt[w * 8 + lr4][k0 + lc4];
                float b1f = kt[w * 8 + lr4][k0 + 4 + lc4];
                unsigned bh0, bl0, bh1, bl1;
                tf_split(b0f, bh0, bl0);
                tf_split(b1f, bh1, bl1);
                mma_tf32(c0, c1, c2, c3, ah0, ah1, ah2, ah3, bh0, bh1);
                mma_tf32(c0, c1, c2, c3, ah0, ah1, ah2, ah3, bl0, bl1);
                mma_tf32(c0, c1, c2, c3, al0, al1, al2, al3, bh0, bh1);
            }
            const int n = w * 8 + lc4 * 2;
            ptT[lr4    ][n    ] = (n     < rows) ? c0 : -1e30f;
            ptT[lr4    ][n + 1] = (n + 1 < rows) ? c1 : -1e30f;
            ptT[lr4 + 8][n    ] = (n     < rows) ? c2 : -1e30f;
            ptT[lr4 + 8][n + 1] = (n + 1 < rows) ? c3 : -1e30f;
        }
        __syncthreads();

        // ---- softmax partial: thread = (q=pq, seg=dc) over 4 scores ----
        {
            float4 p = *(const float4*)&ptT[pq][dc * 4];
            float mt = fmaxf(fmaxf(p.x, p.y), fmaxf(p.z, p.w));
            #pragma unroll
            for (int s = 8; s >= 1; s >>= 1)
                mt = fmaxf(mt, __shfl_xor_sync(0xffffffffu, mt, s, 16));
            const float mo = m_run[pq];
            const float mn = fmaxf(mo, mt);
            const float fc = __expf(mo - mn);
            p.x = __expf(p.x - mn); p.y = __expf(p.y - mn);
            p.z = __expf(p.z - mn); p.w = __expf(p.w - mn);
            *(float4*)&ptT[pq][dc * 4] = p;
            float ss = p.x + p.y + p.z + p.w;
            #pragma unroll
            for (int s = 8; s >= 1; s >>= 1)
                ss += __shfl_xor_sync(0xffffffffu, ss, s, 16);
            if (dc == 0) {
                m_run[pq] = mn;
                fac_s[pq] = fc;
                l_run[pq] = l_run[pq] * fc + ss;
            }
        }
        __syncthreads();

        // ---- AV via 3xTF32 mma: warp w -> output dims w*8..w*8+7 ----
        {
            const float f0 = fac_s[lr4];
            const float f1 = fac_s[lr4 + 8];
            oc0 *= f0; oc1 *= f0; oc2 *= f1; oc3 *= f1;

            #pragma unroll
            for (int ks = 0; ks < 8; ks++) {
                const int k0 = ks * 8;
                float af0 = ptT[lr4    ][k0 + lc4];
                float af1 = ptT[lr4 + 8][k0 + lc4];
                float af2 = ptT[lr4    ][k0 + 4 + lc4];
                float af3 = ptT[lr4 + 8][k0 + 4 + lc4];
                unsigned ah0, al0, ah1, al1, ah2, al2, ah3, al3;
                tf_split(af0, ah0, al0);
                tf_split(af1, ah1, al1);
                tf_split(af2, ah2, al2);
                tf_split(af3, ah3, al3);
                float b0f = vt[k0 + lc4    ][w * 8 + lr4];
                float b1f = vt[k0 + 4 + lc4][w * 8 + lr4];
                unsigned bh0, bl0, bh1, bl1;
                tf_split(b0f, bh0, bl0);
                tf_split(b1f, bh1, bl1);
                mma_tf32(oc0, oc1, oc2, oc3, ah0, ah1, ah2, ah3, bh0, bh1);
                mma_tf32(oc0, oc1, oc2, oc3, ah0, ah1, ah2, ah3, bl0, bl1);
                mma_tf32(oc0, oc1, oc2, oc3, al0, al1, al2, al3, bh0, bh1);
            }
        }
    }

    // ---- write partials ----
    {
        const size_t pbase = (size_t)blockIdx.x * 1024;
        const int d = w * 8 + lc4 * 2;
        *(float2*)&g_po[pbase + lr4       * 64 + d] = make_float2(oc0, oc1);
        *(float2*)&g_po[pbase + (lr4 + 8) * 64 + d] = make_float2(oc2, oc3);
    }
    if (tid < 16) {
        g_pm[blockIdx.x * 16 + tid] = m_run[tid];
        g_pl[blockIdx.x * 16 + tid] = l_run[tid];
    }
}

// ---------------------------------------------------------------------------
// Combine split partials -> g_obuf [B,S,H*hd]
// ---------------------------------------------------------------------------
__global__ __launch_bounds__(256)
void attn_reduce_kernel() {
    const int bh = blockIdx.x;
    const int tid = threadIdx.x;
    const int pq = tid >> 4, dc = tid & 15;
    const int base = bh * NSPLIT;

    float mm = -1e30f;
    #pragma unroll
    for (int s = 0; s < NSPLIT; s++)
        mm = fmaxf(mm, g_pm[(base + s) * 16 + pq]);

    float4 acc = make_float4(0.f, 0.f, 0.f, 0.f);
    float l = 0.f;
    #pragma unroll
    for (int s = 0; s < NSPLIT; s++) {
        float w = __expf(g_pm[(base + s) * 16 + pq] - mm);
        float4 o = *(const float4*)&g_po[(size_t)(base + s) * 1024 + pq * 64 + dc * 4];
        acc.x += w * o.x; acc.y += w * o.y;
        acc.z += w * o.z; acc.w += w * o.w;
        l += w * g_pl[(base + s) * 16 + pq];
    }
    float inv = 1.0f / l;
    const int b = bh >> 4, h = bh & 15;
    float4 r = make_float4(acc.x * inv, acc.y * inv, acc.z * inv, acc.w * inv);
    *(float4*)&g_obuf[(size_t)(b * 16 + pq) * D_MODEL + h * 64 + dc * 4] = r;
}

// ---------------------------------------------------------------------------
extern "C" void kernel_launch(void* const* d_in, const int* in_sizes, int n_in,
                              void* d_out, int out_size) {
    const float* x       = (const float*)d_in[0];
    const float* cache_k = (const float*)d_in[1];
    const float* cache_v = (const float*)d_in[2];
    const float* qkv_w   = (const float*)d_in[3];
    const float* qkv_b   = (const float*)d_in[4];
    const float* out_w   = (const float*)d_in[5];
    const float* out_b   = (const float*)d_in[6];

    float* out   = (float*)d_out;
    float* out_y = out + OUT_Y_OFF;
    float* out_k = out + OUT_K_OFF;
    float* out_v = out + OUT_V_OFF;

    float *qkv_p = nullptr, *obuf_p = nullptr;
    cudaGetSymbolAddress((void**)&qkv_p,  g_qkv);
    cudaGetSymbolAddress((void**)&obuf_p, g_obuf);

    // 1) QKV projection -> g_qkv [256,3072]  (3xTF32 + cp.async pipeline)
    gemm_tf32_kernel<<<dim3(3072 / 64, M_ROWS / 64), 256>>>(
        x, qkv_w, qkv_b, qkv_p, 3072, D_MODEL);

    // 2) Append new K/V rows into out_k/out_v tails
    scatter_newkv_kernel<<<256, 256>>>(out_k, out_v);

    // 3) Fused attention + cache copy-out (split-KV x4, 3xTF32 tensor cores)
    attn_split_kernel<<<B_SZ * H_SZ * NSPLIT, 256>>>(cache_k, cache_v, out_k, out_v);

    // 4) Combine splits -> g_obuf
    attn_reduce_kernel<<<B_SZ * H_SZ, 256>>>();

    // 5) Output projection -> y  (3xTF32 + cp.async pipeline)
    gemm_tf32_kernel<<<dim3(D_MODEL / 64, M_ROWS / 64), 256>>>(
        obuf_p, out_w, out_b, out_y, D_MODEL, D_MODEL);
}

// round 10
// speedup vs baseline: 1.2407x; 1.0923x over previous
#include <cuda_runtime.h>
#include <cuda_bf16.h>
#include <cstddef>

// Problem constants
#define B_SZ    16
#define S_SZ    16
#define H_SZ    16
#define HD      64
#define D_MODEL 1024
#define PAST    4096
#define L_TOT   4112
#define M_ROWS  256
#define NSPLIT  4
#define TILE    32

// Output layout offsets (floats): y | k | v
#define OUT_Y_OFF 0
#define OUT_K_OFF (256*1024)
#define OUT_V_OFF (OUT_K_OFF + 256*4112*64)

// cp.async helpers
__device__ __forceinline__ unsigned smem_u32(const void* p) {
    return (unsigned)__cvta_generic_to_shared(p);
}
#define CP_ASYNC16(dst_u32, src_ptr) \
    asm volatile("cp.async.cg.shared.global [%0], [%1], 16;\n" \
                 :: "r"(dst_u32), "l"(src_ptr))
#define CP_COMMIT() asm volatile("cp.async.commit_group;\n" ::)
#define CP_WAIT1()  asm volatile("cp.async.wait_group 1;\n" ::)
#define CP_WAIT0()  asm volatile("cp.async.wait_group 0;\n" ::)

// Scratch (device globals; no allocations allowed)
__device__ float g_qkv [M_ROWS * 3 * D_MODEL];     // [256, 3072]
__device__ float g_obuf[M_ROWS * D_MODEL];         // [256, 1024]
__device__ float g_po  [256 * NSPLIT * 16 * 64];
__device__ float g_pm  [256 * NSPLIT * 16];
__device__ float g_pl  [256 * NSPLIT * 16];

// ---- tf32 helpers --------------------------------------------------------
__device__ __forceinline__ unsigned f2tf(float x) {
    unsigned r; asm("cvt.rna.tf32.f32 %0, %1;" : "=r"(r) : "f"(x)); return r;
}
__device__ __forceinline__ void tf_split(float x, unsigned& hi, unsigned& lo) {
    hi = f2tf(x);
    lo = f2tf(x - __uint_as_float(hi));
}
__device__ __forceinline__ void mma_tf32(float& c0, float& c1, float& c2, float& c3,
                                         unsigned a0, unsigned a1, unsigned a2, unsigned a3,
                                         unsigned b0, unsigned b1) {
    asm volatile(
        "mma.sync.aligned.m16n8k8.row.col.f32.tf32.tf32.f32 "
        "{%0,%1,%2,%3}, {%4,%5,%6,%7}, {%8,%9}, {%0,%1,%2,%3};\n"
        : "+f"(c0), "+f"(c1), "+f"(c2), "+f"(c3)
        : "r"(a0), "r"(a1), "r"(a2), "r"(a3), "r"(b0), "r"(b1));
}

// ---------------------------------------------------------------------------
// Tensor-core GEMM (3xTF32) with cp.async double-buffered staging.
// (unchanged from round 9 — proven)
// ---------------------------------------------------------------------------
__global__ __launch_bounds__(256)
void gemm_tf32_kernel(const float* __restrict__ A, const float* __restrict__ W,
                      const float* __restrict__ bias, float* __restrict__ C,
                      int N, int K) {
    __shared__ __align__(16) float As[2][64][20];
    __shared__ __align__(16) float Bs[2][64][20];

    const int tid = threadIdx.x;
    const int w   = tid >> 5;
    const int L   = tid & 31;
    const int lr4 = L >> 2;
    const int lc4 = L & 3;
    const int mf  = w >> 1;
    const int nh  = w & 1;

    const int m0 = blockIdx.y * 64;
    const int n0 = blockIdx.x * 64;

    const int srow = tid >> 2;
    const int sch  = (tid & 3) * 4;

    float acc[4][4];
    #pragma unroll
    for (int i = 0; i < 4; i++)
        #pragma unroll
        for (int j = 0; j < 4; j++) acc[i][j] = 0.f;

    const int mbase = mf * 16;
    const int nbase = nh * 32;
    const int niter = K / 16;

    CP_ASYNC16(smem_u32(&As[0][srow][sch]), &A[(size_t)(m0 + srow) * K + sch]);
    CP_ASYNC16(smem_u32(&Bs[0][srow][sch]), &W[(size_t)(n0 + srow) * K + sch]);
    CP_COMMIT();

    for (int t = 0; t < niter; t++) {
        const int bb = t & 1;

        if (t + 1 < niter) {
            const int k1 = (t + 1) * 16;
            CP_ASYNC16(smem_u32(&As[bb ^ 1][srow][sch]),
                       &A[(size_t)(m0 + srow) * K + k1 + sch]);
            CP_ASYNC16(smem_u32(&Bs[bb ^ 1][srow][sch]),
                       &W[(size_t)(n0 + srow) * K + k1 + sch]);
            CP_COMMIT();
            CP_WAIT1();
        } else {
            CP_WAIT0();
        }
        __syncthreads();

        #pragma unroll
        for (int ks = 0; ks < 2; ks++) {
            const int kk = ks * 8;
            float af0 = As[bb][mbase + lr4    ][kk + lc4];
            float af1 = As[bb][mbase + lr4 + 8][kk + lc4];
            float af2 = As[bb][mbase + lr4    ][kk + 4 + lc4];
            float af3 = As[bb][mbase + lr4 + 8][kk + 4 + lc4];
            unsigned ah0, al0, ah1, al1, ah2, al2, ah3, al3;
            tf_split(af0, ah0, al0);
            tf_split(af1, ah1, al1);
            tf_split(af2, ah2, al2);
            tf_split(af3, ah3, al3);

            #pragma unroll
            for (int nf = 0; nf < 4; nf++) {
                const int nn = nbase + nf * 8 + lr4;
                float bf0 = Bs[bb][nn][kk + lc4];
                float bf1 = Bs[bb][nn][kk + 4 + lc4];
                unsigned bh0, bl0, bh1, bl1;
                tf_split(bf0, bh0, bl0);
                tf_split(bf1, bh1, bl1);
                mma_tf32(acc[nf][0], acc[nf][1], acc[nf][2], acc[nf][3],
                         ah0, ah1, ah2, ah3, bh0, bh1);
                mma_tf32(acc[nf][0], acc[nf][1], acc[nf][2], acc[nf][3],
                         ah0, ah1, ah2, ah3, bl0, bl1);
                mma_tf32(acc[nf][0], acc[nf][1], acc[nf][2], acc[nf][3],
                         al0, al1, al2, al3, bh0, bh1);
            }
        }
        __syncthreads();
    }

    const int row0 = m0 + mbase + lr4;
    #pragma unroll
    for (int nf = 0; nf < 4; nf++) {
        const int n = n0 + nbase + nf * 8 + lc4 * 2;
        float2 bb2 = *(const float2*)&bias[n];
        *(float2*)&C[(size_t)row0 * N + n] =
            make_float2(acc[nf][0] + bb2.x, acc[nf][1] + bb2.y);
        *(float2*)&C[(size_t)(row0 + 8) * N + n] =
            make_float2(acc[nf][2] + bb2.x, acc[nf][3] + bb2.y);
    }
}

// ---------------------------------------------------------------------------
// Scatter freshly projected K/V rows into positions [4096, 4112).
// ---------------------------------------------------------------------------
__global__ __launch_bounds__(256)
void scatter_newkv_kernel(float* __restrict__ Kd, float* __restrict__ Vd) {
    const unsigned i = blockIdx.x * 256u + threadIdx.x;    // < 65536
    const unsigned c = i & 15u;
    const unsigned s = (i >> 4) & 15u;
    const unsigned h = (i >> 8) & 15u;
    const unsigned b = i >> 12;
    const size_t qoff = (size_t)(b * 16 + s) * 3072 + h * 64 + c * 4;
    const size_t doff = ((size_t)(b * 16 + h) * L_TOT + PAST + s) * 64 + c * 4;
    *(float4*)&Kd[doff] = *(const float4*)&g_qkv[qoff + 1024];
    *(float4*)&Vd[doff] = *(const float4*)&g_qkv[qoff + 2048];
}

// ---------------------------------------------------------------------------
// Fused attention + cache copy-out, split-KV x4, 3xTF32 tensor cores,
// cp.async double-buffered 32-row tiles. Warps 0-3 compute scores while
// warps 4-7 copy the staged tile out to out_k/out_v (overlapped).
// ---------------------------------------------------------------------------
__global__ __launch_bounds__(256)
void attn_split_kernel(const float* __restrict__ cache_k,
                       const float* __restrict__ cache_v,
                       float* __restrict__ out_k,
                       float* __restrict__ out_v) {
    __shared__ unsigned qh[16][68];
    __shared__ unsigned ql[16][68];
    __shared__ __align__(16) float kt[2][TILE][68];
    __shared__ __align__(16) float vt[2][TILE][68];
    __shared__ float ptT[16][36];
    __shared__ float m_run[16], l_run[16], fac_s[16];

    const int tid   = threadIdx.x;
    const int bh    = blockIdx.x >> 2;
    const int split = blockIdx.x & 3;
    const int b = bh >> 4, h = bh & 15;

    const int w   = tid >> 5;          // warp 0..7
    const int L   = tid & 31;
    const int lr4 = L >> 2;            // 0..7
    const int lc4 = L & 3;             // 0..3

    // ---- load q, scale by 1/8, split hi/lo into smem ----
    {
        const int q = tid >> 4, c4 = tid & 15;
        float4 qv = *(const float4*)&g_qkv[(size_t)(b * 16 + q) * 3072 + h * 64 + c4 * 4];
        qv.x *= 0.125f; qv.y *= 0.125f; qv.z *= 0.125f; qv.w *= 0.125f;
        unsigned hi, lo;
        tf_split(qv.x, hi, lo); qh[q][c4 * 4 + 0] = hi; ql[q][c4 * 4 + 0] = lo;
        tf_split(qv.y, hi, lo); qh[q][c4 * 4 + 1] = hi; ql[q][c4 * 4 + 1] = lo;
        tf_split(qv.z, hi, lo); qh[q][c4 * 4 + 2] = hi; ql[q][c4 * 4 + 2] = lo;
        tf_split(qv.w, hi, lo); qh[q][c4 * 4 + 3] = hi; ql[q][c4 * 4 + 3] = lo;
    }
    if (tid < 16) { m_run[tid] = -1e30f; l_run[tid] = 0.0f; }

    const int chunk0 = split * 1024;
    const int nrows  = (split == 3) ? 1040 : 1024;
    const int ntiles = (split == 3) ? 33 : 32;
    const size_t cbase = (size_t)bh * (PAST * 64);
    const size_t obase = (size_t)bh * (L_TOT * 64);

    // staging mapping: 2 rows per thread per tensor (rows sr, sr+16)
    const int sr = tid >> 4;           // 0..15
    const int sc = tid & 15;           // float4 col

    // softmax mapping
    const int pq = tid >> 4;           // query 0..15
    const int dc = tid & 15;           // 2-score segment

    // O fragment (dims w*8 + lc4*2, +1 ; rows lr4, lr4+8)
    float oc0 = 0.f, oc1 = 0.f, oc2 = 0.f, oc3 = 0.f;

    // ---- stage one tile via cp.async ----
    auto stage = [&](int t, int bb) {
        const int l0 = chunk0 + t * TILE;
        const int rows = min(TILE, chunk0 + nrows - l0);
        #pragma unroll
        for (int i = 0; i < 2; i++) {
            const int r = sr + i * 16;
            if (r < rows) {
                const int gl = l0 + r;
                const size_t off = (size_t)gl * 64 + sc * 4;
                const float* ksrc = (gl < PAST) ? (cache_k + cbase + off)
                                                : (out_k + obase + off);
                const float* vsrc = (gl < PAST) ? (cache_v + cbase + off)
                                                : (out_v + obase + off);
                CP_ASYNC16(smem_u32(&kt[bb][r][sc * 4]), ksrc);
                CP_ASYNC16(smem_u32(&vt[bb][r][sc * 4]), vsrc);
            }
        }
    };

    stage(0, 0);
    CP_COMMIT();

    for (int t = 0; t < ntiles; t++) {
        const int bb   = t & 1;
        const int l0   = chunk0 + t * TILE;
        const int rows = min(TILE, chunk0 + nrows - l0);   // 32 or 16

        __syncthreads();   // buffer bb^1 fully consumed (tile t-1)

        if (t + 1 < ntiles) {
            stage(t + 1, bb ^ 1);
            CP_COMMIT();
            CP_WAIT1();    // group t complete; t+1 in flight
        } else {
            CP_WAIT0();
        }
        __syncthreads();   // staged tile visible

        if (w < 4) {
            // ---- scores via 3xTF32 mma: warp w -> KV rows w*8..w*8+7 ----
            float c0 = 0.f, c1 = 0.f, c2 = 0.f, c3 = 0.f;
            #pragma unroll
            for (int ks = 0; ks < 8; ks++) {
                const int k0 = ks * 8;
                unsigned ah0 = qh[lr4    ][k0 + lc4];
                unsigned ah1 = qh[lr4 + 8][k0 + lc4];
                unsigned ah2 = qh[lr4    ][k0 + 4 + lc4];
                unsigned ah3 = qh[lr4 + 8][k0 + 4 + lc4];
                unsigned al0 = ql[lr4    ][k0 + lc4];
                unsigned al1 = ql[lr4 + 8][k0 + lc4];
                unsigned al2 = ql[lr4    ][k0 + 4 + lc4];
                unsigned al3 = ql[lr4 + 8][k0 + 4 + lc4];
                float b0f = kt[bb][w * 8 + lr4][k0 + lc4];
                float b1f = kt[bb][w * 8 + lr4][k0 + 4 + lc4];
                unsigned bh0, bl0, bh1, bl1;
                tf_split(b0f, bh0, bl0);
                tf_split(b1f, bh1, bl1);
                mma_tf32(c0, c1, c2, c3, ah0, ah1, ah2, ah3, bh0, bh1);
                mma_tf32(c0, c1, c2, c3, ah0, ah1, ah2, ah3, bl0, bl1);
                mma_tf32(c0, c1, c2, c3, al0, al1, al2, al3, bh0, bh1);
            }
            const int n = w * 8 + lc4 * 2;
            ptT[lr4    ][n    ] = (n     < rows) ? c0 : -1e30f;
            ptT[lr4    ][n + 1] = (n + 1 < rows) ? c1 : -1e30f;
            ptT[lr4 + 8][n    ] = (n     < rows) ? c2 : -1e30f;
            ptT[lr4 + 8][n + 1] = (n + 1 < rows) ? c3 : -1e30f;
        } else {
            // ---- copy-out staged cache rows to output KV (overlapped) ----
            const int wtid = tid - 128;        // 0..127
            const int cr = wtid >> 4;          // base row 0..7
            const int cc = wtid & 15;          // float4 col
            #pragma unroll
            for (int j = 0; j < 4; j++) {
                const int r = cr + j * 8;
                const int gl = l0 + r;
                if (r < rows && gl < PAST) {
                    const size_t off = (size_t)gl * 64 + cc * 4;
                    *(float4*)&out_k[obase + off] = *(const float4*)&kt[bb][r][cc * 4];
                    *(float4*)&out_v[obase + off] = *(const float4*)&vt[bb][r][cc * 4];
                }
            }
        }
        __syncthreads();

        // ---- softmax partial: thread = (q=pq, seg=dc) over 2 scores ----
        {
            float2 p = *(const float2*)&ptT[pq][dc * 2];
            float mt = fmaxf(p.x, p.y);
            #pragma unroll
            for (int s = 8; s >= 1; s >>= 1)
                mt = fmaxf(mt, __shfl_xor_sync(0xffffffffu, mt, s, 16));
            const float mo = m_run[pq];
            const float mn = fmaxf(mo, mt);
            const float fc = __expf(mo - mn);
            p.x = __expf(p.x - mn);
            p.y = __expf(p.y - mn);
            *(float2*)&ptT[pq][dc * 2] = p;
            float ss = p.x + p.y;
            #pragma unroll
            for (int s = 8; s >= 1; s >>= 1)
                ss += __shfl_xor_sync(0xffffffffu, ss, s, 16);
            if (dc == 0) {
                m_run[pq] = mn;
                fac_s[pq] = fc;
                l_run[pq] = l_run[pq] * fc + ss;
            }
        }
        __syncthreads();

        // ---- AV via 3xTF32 mma: warp w -> output dims w*8..w*8+7 ----
        {
            const float f0 = fac_s[lr4];
            const float f1 = fac_s[lr4 + 8];
            oc0 *= f0; oc1 *= f0; oc2 *= f1; oc3 *= f1;

            #pragma unroll
            for (int ks = 0; ks < 4; ks++) {
                const int k0 = ks * 8;
                float af0 = ptT[lr4    ][k0 + lc4];
                float af1 = ptT[lr4 + 8][k0 + lc4];
                float af2 = ptT[lr4    ][k0 + 4 + lc4];
                float af3 = ptT[lr4 + 8][k0 + 4 + lc4];
                unsigned ah0, al0, ah1, al1, ah2, al2, ah3, al3;
                tf_split(af0, ah0, al0);
                tf_split(af1, ah1, al1);
                tf_split(af2, ah2, al2);
                tf_split(af3, ah3, al3);
                float b0f = vt[bb][k0 + lc4    ][w * 8 + lr4];
                float b1f = vt[bb][k0 + 4 + lc4][w * 8 + lr4];
                unsigned bh0, bl0, bh1, bl1;
                tf_split(b0f, bh0, bl0);
                tf_split(b1f, bh1, bl1);
                mma_tf32(oc0, oc1, oc2, oc3, ah0, ah1, ah2, ah3, bh0, bh1);
                mma_tf32(oc0, oc1, oc2, oc3, ah0, ah1, ah2, ah3, bl0, bl1);
                mma_tf32(oc0, oc1, oc2, oc3, al0, al1, al2, al3, bh0, bh1);
            }
        }
    }

    // ---- write partials ----
    {
        const size_t pbase = (size_t)blockIdx.x * 1024;
        const int d = w * 8 + lc4 * 2;
        *(float2*)&g_po[pbase + lr4       * 64 + d] = make_float2(oc0, oc1);
        *(float2*)&g_po[pbase + (lr4 + 8) * 64 + d] = make_float2(oc2, oc3);
    }
    if (tid < 16) {
        g_pm[blockIdx.x * 16 + tid] = m_run[tid];
        g_pl[blockIdx.x * 16 + tid] = l_run[tid];
    }
}

// ---------------------------------------------------------------------------
// Combine split partials -> g_obuf [B,S,H*hd]
// ---------------------------------------------------------------------------
__global__ __launch_bounds__(256)
void attn_reduce_kernel() {
    const int bh = blockIdx.x;
    const int tid = threadIdx.x;
    const int pq = tid >> 4, dc = tid & 15;
    const int base = bh * NSPLIT;

    float mm = -1e30f;
    #pragma unroll
    for (int s = 0; s < NSPLIT; s++)
        mm = fmaxf(mm, g_pm[(base + s) * 16 + pq]);

    float4 acc = make_float4(0.f, 0.f, 0.f, 0.f);
    float l = 0.f;
    #pragma unroll
    for (int s = 0; s < NSPLIT; s++) {
        float w = __expf(g_pm[(base + s) * 16 + pq] - mm);
        float4 o = *(const float4*)&g_po[(size_t)(base + s) * 1024 + pq * 64 + dc * 4];
        acc.x += w * o.x; acc.y += w * o.y;
        acc.z += w * o.z; acc.w += w * o.w;
        l += w * g_pl[(base + s) * 16 + pq];
    }
    float inv = 1.0f / l;
    const int b = bh >> 4, h = bh & 15;
    float4 r = make_float4(acc.x * inv, acc.y * inv, acc.z * inv, acc.w * inv);
    *(float4*)&g_obuf[(size_t)(b * 16 + pq) * D_MODEL + h * 64 + dc * 4] = r;
}

// ---------------------------------------------------------------------------
extern "C" void kernel_launch(void* const* d_in, const int* in_sizes, int n_in,
                              void* d_out, int out_size) {
    const float* x       = (const float*)d_in[0];
    const float* cache_k = (const float*)d_in[1];
    const float* cache_v = (const float*)d_in[2];
    const float* qkv_w   = (const float*)d_in[3];
    const float* qkv_b   = (const float*)d_in[4];
    const float* out_w   = (const float*)d_in[5];
    const float* out_b   = (const float*)d_in[6];

    float* out   = (float*)d_out;
    float* out_y = out + OUT_Y_OFF;
    float* out_k = out + OUT_K_OFF;
    float* out_v = out + OUT_V_OFF;

    float *qkv_p = nullptr, *obuf_p = nullptr;
    cudaGetSymbolAddress((void**)&qkv_p,  g_qkv);
    cudaGetSymbolAddress((void**)&obuf_p, g_obuf);

    // 1) QKV projection -> g_qkv [256,3072]  (3xTF32 + cp.async pipeline)
    gemm_tf32_kernel<<<dim3(3072 / 64, M_ROWS / 64), 256>>>(
        x, qkv_w, qkv_b, qkv_p, 3072, D_MODEL);

    // 2) Append new K/V rows into out_k/out_v tails
    scatter_newkv_kernel<<<256, 256>>>(out_k, out_v);

    // 3) Fused attention + cache copy-out (split-KV x4, TC + cp.async)
    attn_split_kernel<<<B_SZ * H_SZ * NSPLIT, 256>>>(cache_k, cache_v, out_k, out_v);

    // 4) Combine splits -> g_obuf
    attn_reduce_kernel<<<B_SZ * H_SZ, 256>>>();

    // 5) Output projection -> y  (3xTF32 + cp.async pipeline)
    gemm_tf32_kernel<<<dim3(D_MODEL / 64, M_ROWS / 64), 256>>>(
        obuf_p, out_w, out_b, out_y, D_MODEL, D_MODEL);
}

// round 11
// speedup vs baseline: 1.2567x; 1.0129x over previous
#include <cuda_runtime.h>
#include <cuda_bf16.h>
#include <cstddef>

// Problem constants
#define B_SZ    16
#define S_SZ    16
#define H_SZ    16
#define HD      64
#define D_MODEL 1024
#define PAST    4096
#define L_TOT   4112
#define M_ROWS  256
#define NSPLIT  8
#define TILE    32

// Output layout offsets (floats): y | k | v
#define OUT_Y_OFF 0
#define OUT_K_OFF (256*1024)
#define OUT_V_OFF (OUT_K_OFF + 256*4112*64)

// cp.async helpers
__device__ __forceinline__ unsigned smem_u32(const void* p) {
    return (unsigned)__cvta_generic_to_shared(p);
}
#define CP_ASYNC16(dst_u32, src_ptr) \
    asm volatile("cp.async.cg.shared.global [%0], [%1], 16;\n" \
                 :: "r"(dst_u32), "l"(src_ptr))
#define CP_COMMIT() asm volatile("cp.async.commit_group;\n" ::)
#define CP_WAIT3()  asm volatile("cp.async.wait_group 3;\n" ::)
#define CP_WAIT1()  asm volatile("cp.async.wait_group 1;\n" ::)
#define CP_WAIT0()  asm volatile("cp.async.wait_group 0;\n" ::)

// Scratch (device globals; no allocations allowed)
__device__ float g_qkv [M_ROWS * 3 * D_MODEL];     // [256, 3072]
__device__ float g_obuf[M_ROWS * D_MODEL];         // [256, 1024]
__device__ float g_po  [256 * NSPLIT * 16 * 64];
__device__ float g_pm  [256 * NSPLIT * 16];
__device__ float g_pl  [256 * NSPLIT * 16];

// ---- tf32 helpers --------------------------------------------------------
__device__ __forceinline__ unsigned f2tf(float x) {
    unsigned r; asm("cvt.rna.tf32.f32 %0, %1;" : "=r"(r) : "f"(x)); return r;
}
__device__ __forceinline__ void tf_split(float x, unsigned& hi, unsigned& lo) {
    hi = f2tf(x);
    lo = f2tf(x - __uint_as_float(hi));
}
__device__ __forceinline__ void mma_tf32(float& c0, float& c1, float& c2, float& c3,
                                         unsigned a0, unsigned a1, unsigned a2, unsigned a3,
                                         unsigned b0, unsigned b1) {
    asm volatile(
        "mma.sync.aligned.m16n8k8.row.col.f32.tf32.tf32.f32 "
        "{%0,%1,%2,%3}, {%4,%5,%6,%7}, {%8,%9}, {%0,%1,%2,%3};\n"
        : "+f"(c0), "+f"(c1), "+f"(c2), "+f"(c3)
        : "r"(a0), "r"(a1), "r"(a2), "r"(a3), "r"(b0), "r"(b1));
}

// ---------------------------------------------------------------------------
// Tensor-core GEMM (3xTF32), cp.async 4-stage pipeline.
// C[M,N] = A[M,K] @ W[N,K]^T + bias[N]. 64x64 tile, 256 threads (8 warps).
// If sK != nullptr (QKV projection), columns n in [1024,2048) are also
// scattered into sK (new K rows) and [2048,3072) into sV (new V rows).
// ---------------------------------------------------------------------------
__global__ __launch_bounds__(256)
void gemm_tf32_kernel(const float* __restrict__ A, const float* __restrict__ W,
                      const float* __restrict__ bias, float* __restrict__ C,
                      int N, int K, float* __restrict__ sK, float* __restrict__ sV) {
    __shared__ __align__(16) float As[4][64][20];
    __shared__ __align__(16) float Bs[4][64][20];

    const int tid = threadIdx.x;
    const int w   = tid >> 5;
    const int L   = tid & 31;
    const int lr4 = L >> 2;
    const int lc4 = L & 3;
    const int mf  = w >> 1;
    const int nh  = w & 1;

    const int m0 = blockIdx.y * 64;
    const int n0 = blockIdx.x * 64;

    const int srow = tid >> 2;
    const int sch  = (tid & 3) * 4;

    float acc[4][4];
    #pragma unroll
    for (int i = 0; i < 4; i++)
        #pragma unroll
        for (int j = 0; j < 4; j++) acc[i][j] = 0.f;

    const int mbase = mf * 16;
    const int nbase = nh * 32;
    const int niter = K / 16;   // 64 — always > 3

    // prologue: stage slabs 0..2 (one commit group each)
    #pragma unroll
    for (int p = 0; p < 3; p++) {
        CP_ASYNC16(smem_u32(&As[p][srow][sch]), &A[(size_t)(m0 + srow) * K + p * 16 + sch]);
        CP_ASYNC16(smem_u32(&Bs[p][srow][sch]), &W[(size_t)(n0 + srow) * K + p * 16 + sch]);
        CP_COMMIT();
    }

    for (int t = 0; t < niter; t++) {
        const int bb = t & 3;

        // stage slab t+3 into buf (t+3)&3 (holds slab t-1: consumed last iter)
        if (t + 3 < niter) {
            const int k1 = (t + 3) * 16;
            const int pb = (t + 3) & 3;
            CP_ASYNC16(smem_u32(&As[pb][srow][sch]),
                       &A[(size_t)(m0 + srow) * K + k1 + sch]);
            CP_ASYNC16(smem_u32(&Bs[pb][srow][sch]),
                       &W[(size_t)(n0 + srow) * K + k1 + sch]);
        }
        CP_COMMIT();         // group count stays aligned (may be empty)
        CP_WAIT3();          // <=3 pending -> slab t complete
        __syncthreads();     // staged slab visible to all

        #pragma unroll
        for (int ks = 0; ks < 2; ks++) {
            const int kk = ks * 8;
            float af0 = As[bb][mbase + lr4    ][kk + lc4];
            float af1 = As[bb][mbase + lr4 + 8][kk + lc4];
            float af2 = As[bb][mbase + lr4    ][kk + 4 + lc4];
            float af3 = As[bb][mbase + lr4 + 8][kk + 4 + lc4];
            unsigned ah0, al0, ah1, al1, ah2, al2, ah3, al3;
            tf_split(af0, ah0, al0);
            tf_split(af1, ah1, al1);
            tf_split(af2, ah2, al2);
            tf_split(af3, ah3, al3);

            #pragma unroll
            for (int nf = 0; nf < 4; nf++) {
                const int nn = nbase + nf * 8 + lr4;
                float bf0 = Bs[bb][nn][kk + lc4];
                float bf1 = Bs[bb][nn][kk + 4 + lc4];
                unsigned bh0, bl0, bh1, bl1;
                tf_split(bf0, bh0, bl0);
                tf_split(bf1, bh1, bl1);
                mma_tf32(acc[nf][0], acc[nf][1], acc[nf][2], acc[nf][3],
                         ah0, ah1, ah2, ah3, bh0, bh1);
                mma_tf32(acc[nf][0], acc[nf][1], acc[nf][2], acc[nf][3],
                         ah0, ah1, ah2, ah3, bl0, bl1);
                mma_tf32(acc[nf][0], acc[nf][1], acc[nf][2], acc[nf][3],
                         al0, al1, al2, al3, bh0, bh1);
            }
        }
        __syncthreads();     // slab consumed; next stage may overwrite
    }

    // epilogue: C frag c0 (m=lr4, n=lc4*2), c1 n+1, c2/c3 m+8; add bias.
    // Optional fused scatter of new K/V rows (QKV projection only).
    const int row0 = m0 + mbase + lr4;
    #pragma unroll
    for (int nf = 0; nf < 4; nf++) {
        const int n = n0 + nbase + nf * 8 + lc4 * 2;
        float2 bb2 = *(const float2*)&bias[n];
        float2 v0 = make_float2(acc[nf][0] + bb2.x, acc[nf][1] + bb2.y);
        float2 v1 = make_float2(acc[nf][2] + bb2.x, acc[nf][3] + bb2.y);
        *(float2*)&C[(size_t)row0 * N + n]       = v0;
        *(float2*)&C[(size_t)(row0 + 8) * N + n] = v1;

        if (sK != nullptr && n >= 1024) {
            const int tt = (n >= 2048) ? (n - 2048) : (n - 1024);
            float* dst = (n >= 2048) ? sV : sK;
            const int hh = tt >> 6, dd = tt & 63;
            // row = b*16 + s  ->  b = row>>4, s = row&15
            const size_t o0 = (((size_t)((row0 >> 4) * 16 + hh) * L_TOT) + PAST + (row0 & 15)) * 64 + dd;
            const int row1 = row0 + 8;
            const size_t o1 = (((size_t)((row1 >> 4) * 16 + hh) * L_TOT) + PAST + (row1 & 15)) * 64 + dd;
            *(float2*)&dst[o0] = v0;
            *(float2*)&dst[o1] = v1;
        }
    }
}

// ---------------------------------------------------------------------------
// Fused attention + cache copy-out, split-KV x8, 3xTF32 tensor cores,
// cp.async double-buffered 32-row tiles, warp-specialized copy-out.
// (body identical to round 10 except split arithmetic)
// ---------------------------------------------------------------------------
__global__ __launch_bounds__(256)
void attn_split_kernel(const float* __restrict__ cache_k,
                       const float* __restrict__ cache_v,
                       float* __restrict__ out_k,
                       float* __restrict__ out_v) {
    __shared__ unsigned qh[16][68];
    __shared__ unsigned ql[16][68];
    __shared__ __align__(16) float kt[2][TILE][68];
    __shared__ __align__(16) float vt[2][TILE][68];
    __shared__ float ptT[16][36];
    __shared__ float m_run[16], l_run[16], fac_s[16];

    const int tid   = threadIdx.x;
    const int bh    = blockIdx.x >> 3;
    const int split = blockIdx.x & 7;
    const int b = bh >> 4, h = bh & 15;

    const int w   = tid >> 5;
    const int L   = tid & 31;
    const int lr4 = L >> 2;
    const int lc4 = L & 3;

    // ---- load q, scale by 1/8, split hi/lo into smem ----
    {
        const int q = tid >> 4, c4 = tid & 15;
        float4 qv = *(const float4*)&g_qkv[(size_t)(b * 16 + q) * 3072 + h * 64 + c4 * 4];
        qv.x *= 0.125f; qv.y *= 0.125f; qv.z *= 0.125f; qv.w *= 0.125f;
        unsigned hi, lo;
        tf_split(qv.x, hi, lo); qh[q][c4 * 4 + 0] = hi; ql[q][c4 * 4 + 0] = lo;
        tf_split(qv.y, hi, lo); qh[q][c4 * 4 + 1] = hi; ql[q][c4 * 4 + 1] = lo;
        tf_split(qv.z, hi, lo); qh[q][c4 * 4 + 2] = hi; ql[q][c4 * 4 + 2] = lo;
        tf_split(qv.w, hi, lo); qh[q][c4 * 4 + 3] = hi; ql[q][c4 * 4 + 3] = lo;
    }
    if (tid < 16) { m_run[tid] = -1e30f; l_run[tid] = 0.0f; }

    const int chunk0 = split * 512;
    const int nrows  = (split == 7) ? 528 : 512;
    const int ntiles = (split == 7) ? 17 : 16;
    const size_t cbase = (size_t)bh * (PAST * 64);
    const size_t obase = (size_t)bh * (L_TOT * 64);

    const int sr = tid >> 4;           // staging rows sr, sr+16
    const int sc = tid & 15;

    const int pq = tid >> 4;           // softmax query
    const int dc = tid & 15;           // softmax segment

    float oc0 = 0.f, oc1 = 0.f, oc2 = 0.f, oc3 = 0.f;

    auto stage = [&](int t, int bb) {
        const int l0 = chunk0 + t * TILE;
        const int rows = min(TILE, chunk0 + nrows - l0);
        #pragma unroll
        for (int i = 0; i < 2; i++) {
            const int r = sr + i * 16;
            if (r < rows) {
                const int gl = l0 + r;
                const size_t off = (size_t)gl * 64 + sc * 4;
                const float* ksrc = (gl < PAST) ? (cache_k + cbase + off)
                                                : (out_k + obase + off);
                const float* vsrc = (gl < PAST) ? (cache_v + cbase + off)
                                                : (out_v + obase + off);
                CP_ASYNC16(smem_u32(&kt[bb][r][sc * 4]), ksrc);
                CP_ASYNC16(smem_u32(&vt[bb][r][sc * 4]), vsrc);
            }
        }
    };

    stage(0, 0);
    CP_COMMIT();

    for (int t = 0; t < ntiles; t++) {
        const int bb   = t & 1;
        const int l0   = chunk0 + t * TILE;
        const int rows = min(TILE, chunk0 + nrows - l0);   // 32 or 16

        __syncthreads();

        if (t + 1 < ntiles) {
            stage(t + 1, bb ^ 1);
            CP_COMMIT();
            CP_WAIT1();
        } else {
            CP_WAIT0();
        }
        __syncthreads();

        if (w < 4) {
            float c0 = 0.f, c1 = 0.f, c2 = 0.f, c3 = 0.f;
            #pragma unroll
            for (int ks = 0; ks < 8; ks++) {
                const int k0 = ks * 8;
                unsigned ah0 = qh[lr4    ][k0 + lc4];
                unsigned ah1 = qh[lr4 + 8][k0 + lc4];
                unsigned ah2 = qh[lr4    ][k0 + 4 + lc4];
                unsigned ah3 = qh[lr4 + 8][k0 + 4 + lc4];
                unsigned al0 = ql[lr4    ][k0 + lc4];
                unsigned al1 = ql[lr4 + 8][k0 + lc4];
                unsigned al2 = ql[lr4    ][k0 + 4 + lc4];
                unsigned al3 = ql[lr4 + 8][k0 + 4 + lc4];
                float b0f = kt[bb][w * 8 + lr4][k0 + lc4];
                float b1f = kt[bb][w * 8 + lr4][k0 + 4 + lc4];
                unsigned bh0, bl0, bh1, bl1;
                tf_split(b0f, bh0, bl0);
                tf_split(b1f, bh1, bl1);
                mma_tf32(c0, c1, c2, c3, ah0, ah1, ah2, ah3, bh0, bh1);
                mma_tf32(c0, c1, c2, c3, ah0, ah1, ah2, ah3, bl0, bl1);
                mma_tf32(c0, c1, c2, c3, al0, al1, al2, al3, bh0, bh1);
            }
            const int n = w * 8 + lc4 * 2;
            ptT[lr4    ][n    ] = (n     < rows) ? c0 : -1e30f;
            ptT[lr4    ][n + 1] = (n + 1 < rows) ? c1 : -1e30f;
            ptT[lr4 + 8][n    ] = (n     < rows) ? c2 : -1e30f;
            ptT[lr4 + 8][n + 1] = (n + 1 < rows) ? c3 : -1e30f;
        } else {
            const int wtid = tid - 128;
            const int cr = wtid >> 4;
            const int cc = wtid & 15;
            #pragma unroll
            for (int j = 0; j < 4; j++) {
                const int r = cr + j * 8;
                const int gl = l0 + r;
                if (r < rows && gl < PAST) {
                    const size_t off = (size_t)gl * 64 + cc * 4;
                    *(float4*)&out_k[obase + off] = *(const float4*)&kt[bb][r][cc * 4];
                    *(float4*)&out_v[obase + off] = *(const float4*)&vt[bb][r][cc * 4];
                }
            }
        }
        __syncthreads();

        {
            float2 p = *(const float2*)&ptT[pq][dc * 2];
            float mt = fmaxf(p.x, p.y);
            #pragma unroll
            for (int s = 8; s >= 1; s >>= 1)
                mt = fmaxf(mt, __shfl_xor_sync(0xffffffffu, mt, s, 16));
            const float mo = m_run[pq];
            const float mn = fmaxf(mo, mt);
            const float fc = __expf(mo - mn);
            p.x = __expf(p.x - mn);
            p.y = __expf(p.y - mn);
            *(float2*)&ptT[pq][dc * 2] = p;
            float ss = p.x + p.y;
            #pragma unroll
            for (int s = 8; s >= 1; s >>= 1)
                ss += __shfl_xor_sync(0xffffffffu, ss, s, 16);
            if (dc == 0) {
                m_run[pq] = mn;
                fac_s[pq] = fc;
                l_run[pq] = l_run[pq] * fc + ss;
            }
        }
        __syncthreads();

        {
            const float f0 = fac_s[lr4];
            const float f1 = fac_s[lr4 + 8];
            oc0 *= f0; oc1 *= f0; oc2 *= f1; oc3 *= f1;

            #pragma unroll
            for (int ks = 0; ks < 4; ks++) {
                const int k0 = ks * 8;
                float af0 = ptT[lr4    ][k0 + lc4];
                float af1 = ptT[lr4 + 8][k0 + lc4];
                float af2 = ptT[lr4    ][k0 + 4 + lc4];
                float af3 = ptT[lr4 + 8][k0 + 4 + lc4];
                unsigned ah0, al0, ah1, al1, ah2, al2, ah3, al3;
                tf_split(af0, ah0, al0);
                tf_split(af1, ah1, al1);
                tf_split(af2, ah2, al2);
                tf_split(af3, ah3, al3);
                float b0f = vt[bb][k0 + lc4    ][w * 8 + lr4];
                float b1f = vt[bb][k0 + 4 + lc4][w * 8 + lr4];
                unsigned bh0, bl0, bh1, bl1;
                tf_split(b0f, bh0, bl0);
                tf_split(b1f, bh1, bl1);
                mma_tf32(oc0, oc1, oc2, oc3, ah0, ah1, ah2, ah3, bh0, bh1);
                mma_tf32(oc0, oc1, oc2, oc3, ah0, ah1, ah2, ah3, bl0, bl1);
                mma_tf32(oc0, oc1, oc2, oc3, al0, al1, al2, al3, bh0, bh1);
            }
        }
    }

    {
        const size_t pbase = (size_t)blockIdx.x * 1024;
        const int d = w * 8 + lc4 * 2;
        *(float2*)&g_po[pbase + lr4       * 64 + d] = make_float2(oc0, oc1);
        *(float2*)&g_po[pbase + (lr4 + 8) * 64 + d] = make_float2(oc2, oc3);
    }
    if (tid < 16) {
        g_pm[blockIdx.x * 16 + tid] = m_run[tid];
        g_pl[blockIdx.x * 16 + tid] = l_run[tid];
    }
}

// ---------------------------------------------------------------------------
// Combine split partials -> g_obuf [B,S,H*hd]
// ---------------------------------------------------------------------------
__global__ __launch_bounds__(256)
void attn_reduce_kernel() {
    const int bh = blockIdx.x;
    const int tid = threadIdx.x;
    const int pq = tid >> 4, dc = tid & 15;
    const int base = bh * NSPLIT;

    float mm = -1e30f;
    #pragma unroll
    for (int s = 0; s < NSPLIT; s++)
        mm = fmaxf(mm, g_pm[(base + s) * 16 + pq]);

    float4 acc = make_float4(0.f, 0.f, 0.f, 0.f);
    float l = 0.f;
    #pragma unroll
    for (int s = 0; s < NSPLIT; s++) {
        float w = __expf(g_pm[(base + s) * 16 + pq] - mm);
        float4 o = *(const float4*)&g_po[(size_t)(base + s) * 1024 + pq * 64 + dc * 4];
        acc.x += w * o.x; acc.y += w * o.y;
        acc.z += w * o.z; acc.w += w * o.w;
        l += w * g_pl[(base + s) * 16 + pq];
    }
    float inv = 1.0f / l;
    const int b = bh >> 4, h = bh & 15;
    float4 r = make_float4(acc.x * inv, acc.y * inv, acc.z * inv, acc.w * inv);
    *(float4*)&g_obuf[(size_t)(b * 16 + pq) * D_MODEL + h * 64 + dc * 4] = r;
}

// ---------------------------------------------------------------------------
extern "C" void kernel_launch(void* const* d_in, const int* in_sizes, int n_in,
                              void* d_out, int out_size) {
    const float* x       = (const float*)d_in[0];
    const float* cache_k = (const float*)d_in[1];
    const float* cache_v = (const float*)d_in[2];
    const float* qkv_w   = (const float*)d_in[3];
    const float* qkv_b   = (const float*)d_in[4];
    const float* out_w   = (const float*)d_in[5];
    const float* out_b   = (const float*)d_in[6];

    float* out   = (float*)d_out;
    float* out_y = out + OUT_Y_OFF;
    float* out_k = out + OUT_K_OFF;
    float* out_v = out + OUT_V_OFF;

    float *qkv_p = nullptr, *obuf_p = nullptr;
    cudaGetSymbolAddress((void**)&qkv_p,  g_qkv);
    cudaGetSymbolAddress((void**)&obuf_p, g_obuf);

    // 1) QKV projection -> g_qkv [256,3072] + fused scatter of new K/V rows
    gemm_tf32_kernel<<<dim3(3072 / 64, M_ROWS / 64), 256>>>(
        x, qkv_w, qkv_b, qkv_p, 3072, D_MODEL, out_k, out_v);

    // 2) Fused attention + cache copy-out (split-KV x8, TC + cp.async)
    attn_split_kernel<<<B_SZ * H_SZ * NSPLIT, 256>>>(cache_k, cache_v, out_k, out_v);

    // 3) Combine splits -> g_obuf
    attn_reduce_kernel<<<B_SZ * H_SZ, 256>>>();

    // 4) Output projection -> y
    gemm_tf32_kernel<<<dim3(D_MODEL / 64, M_ROWS / 64), 256>>>(
        obuf_p, out_w, out_b, out_y, D_MODEL, D_MODEL, nullptr, nullptr);
}

// round 12
// speedup vs baseline: 1.4101x; 1.1220x over previous
#include <cuda_runtime.h>
#include <cuda_bf16.h>
#include <cstddef>

// Problem constants
#define B_SZ    16
#define S_SZ    16
#define H_SZ    16
#define HD      64
#define D_MODEL 1024
#define PAST    4096
#define L_TOT   4112
#define M_ROWS  256
#define NSPLIT  8
#define TILE    32
#define KSPLIT  4

// Output layout offsets (floats): y | k | v
#define OUT_Y_OFF 0
#define OUT_K_OFF (256*1024)
#define OUT_V_OFF (OUT_K_OFF + 256*4112*64)

// cp.async helpers
__device__ __forceinline__ unsigned smem_u32(const void* p) {
    return (unsigned)__cvta_generic_to_shared(p);
}
#define CP_ASYNC16(dst_u32, src_ptr) \
    asm volatile("cp.async.cg.shared.global [%0], [%1], 16;\n" \
                 :: "r"(dst_u32), "l"(src_ptr))
#define CP_COMMIT() asm volatile("cp.async.commit_group;\n" ::)
#define CP_WAIT3()  asm volatile("cp.async.wait_group 3;\n" ::)
#define CP_WAIT1()  asm volatile("cp.async.wait_group 1;\n" ::)
#define CP_WAIT0()  asm volatile("cp.async.wait_group 0;\n" ::)

// Scratch (device globals; no allocations allowed)
__device__ float g_qkv [M_ROWS * 3 * D_MODEL];            // [256, 3072]
__device__ float g_obuf[M_ROWS * D_MODEL];                // [256, 1024]
__device__ float g_part[KSPLIT * M_ROWS * 3 * D_MODEL];   // split-K partials
__device__ float g_po  [256 * NSPLIT * 16 * 64];
__device__ float g_pm  [256 * NSPLIT * 16];
__device__ float g_pl  [256 * NSPLIT * 16];

// ---- tf32 helpers --------------------------------------------------------
__device__ __forceinline__ unsigned f2tf(float x) {
    unsigned r; asm("cvt.rna.tf32.f32 %0, %1;" : "=r"(r) : "f"(x)); return r;
}
__device__ __forceinline__ void tf_split(float x, unsigned& hi, unsigned& lo) {
    hi = f2tf(x);
    lo = f2tf(x - __uint_as_float(hi));
}
__device__ __forceinline__ void mma_tf32(float& c0, float& c1, float& c2, float& c3,
                                         unsigned a0, unsigned a1, unsigned a2, unsigned a3,
                                         unsigned b0, unsigned b1) {
    asm volatile(
        "mma.sync.aligned.m16n8k8.row.col.f32.tf32.tf32.f32 "
        "{%0,%1,%2,%3}, {%4,%5,%6,%7}, {%8,%9}, {%0,%1,%2,%3};\n"
        : "+f"(c0), "+f"(c1), "+f"(c2), "+f"(c3)
        : "r"(a0), "r"(a1), "r"(a2), "r"(a3), "r"(b0), "r"(b1));
}

// ---------------------------------------------------------------------------
// Split-K tensor-core GEMM (3xTF32), cp.async 4-stage pipeline.
// Partial C_kz[M,N] = A[M, kz*K/4 : (kz+1)*K/4] @ W[., same]^T  (no bias).
// Partials land in g_part[(kz*M + row)*N + n].
// ---------------------------------------------------------------------------
__global__ __launch_bounds__(256)
void gemm_tf32_split_kernel(const float* __restrict__ A, const float* __restrict__ W,
                            float* __restrict__ P, int N, int K) {
    __shared__ __align__(16) float As[4][64][20];
    __shared__ __align__(16) float Bs[4][64][20];

    const int tid = threadIdx.x;
    const int w   = tid >> 5;
    const int L   = tid & 31;
    const int lr4 = L >> 2;
    const int lc4 = L & 3;
    const int mf  = w >> 1;
    const int nh  = w & 1;

    const int m0 = blockIdx.y * 64;
    const int n0 = blockIdx.x * 64;
    const int kz = blockIdx.z;
    const int kbase = kz * (K / KSPLIT);

    const int srow = tid >> 2;
    const int sch  = (tid & 3) * 4;

    float acc[4][4];
    #pragma unroll
    for (int i = 0; i < 4; i++)
        #pragma unroll
        for (int j = 0; j < 4; j++) acc[i][j] = 0.f;

    const int mbase = mf * 16;
    const int nbase = nh * 32;
    const int niter = (K / KSPLIT) / 16;   // 16

    #pragma unroll
    for (int p = 0; p < 3; p++) {
        CP_ASYNC16(smem_u32(&As[p][srow][sch]),
                   &A[(size_t)(m0 + srow) * K + kbase + p * 16 + sch]);
        CP_ASYNC16(smem_u32(&Bs[p][srow][sch]),
                   &W[(size_t)(n0 + srow) * K + kbase + p * 16 + sch]);
        CP_COMMIT();
    }

    for (int t = 0; t < niter; t++) {
        const int bb = t & 3;

        if (t + 3 < niter) {
            const int k1 = kbase + (t + 3) * 16;
            const int pb = (t + 3) & 3;
            CP_ASYNC16(smem_u32(&As[pb][srow][sch]),
                       &A[(size_t)(m0 + srow) * K + k1 + sch]);
            CP_ASYNC16(smem_u32(&Bs[pb][srow][sch]),
                       &W[(size_t)(n0 + srow) * K + k1 + sch]);
        }
        CP_COMMIT();
        CP_WAIT3();
        __syncthreads();

        #pragma unroll
        for (int ks = 0; ks < 2; ks++) {
            const int kk = ks * 8;
            float af0 = As[bb][mbase + lr4    ][kk + lc4];
            float af1 = As[bb][mbase + lr4 + 8][kk + lc4];
            float af2 = As[bb][mbase + lr4    ][kk + 4 + lc4];
            float af3 = As[bb][mbase + lr4 + 8][kk + 4 + lc4];
            unsigned ah0, al0, ah1, al1, ah2, al2, ah3, al3;
            tf_split(af0, ah0, al0);
            tf_split(af1, ah1, al1);
            tf_split(af2, ah2, al2);
            tf_split(af3, ah3, al3);

            #pragma unroll
            for (int nf = 0; nf < 4; nf++) {
                const int nn = nbase + nf * 8 + lr4;
                float bf0 = Bs[bb][nn][kk + lc4];
                float bf1 = Bs[bb][nn][kk + 4 + lc4];
                unsigned bh0, bl0, bh1, bl1;
                tf_split(bf0, bh0, bl0);
                tf_split(bf1, bh1, bl1);
                mma_tf32(acc[nf][0], acc[nf][1], acc[nf][2], acc[nf][3],
                         ah0, ah1, ah2, ah3, bh0, bh1);
                mma_tf32(acc[nf][0], acc[nf][1], acc[nf][2], acc[nf][3],
                         ah0, ah1, ah2, ah3, bl0, bl1);
                mma_tf32(acc[nf][0], acc[nf][1], acc[nf][2], acc[nf][3],
                         al0, al1, al2, al3, bh0, bh1);
            }
        }
        __syncthreads();
    }

    const int row0 = m0 + mbase + lr4;
    const size_t pb0 = (size_t)kz * M_ROWS;
    #pragma unroll
    for (int nf = 0; nf < 4; nf++) {
        const int n = n0 + nbase + nf * 8 + lc4 * 2;
        *(float2*)&P[(pb0 + row0) * N + n]       = make_float2(acc[nf][0], acc[nf][1]);
        *(float2*)&P[(pb0 + row0 + 8) * N + n]   = make_float2(acc[nf][2], acc[nf][3]);
    }
}

// ---------------------------------------------------------------------------
// QKV reduce: sum 4 split-K partials + bias -> g_qkv; scatter new K/V rows
// into out_k/out_v tails. 768 blocks x 256 threads, one float4 each.
// ---------------------------------------------------------------------------
__global__ __launch_bounds__(256)
void qkv_reduce_kernel(const float* __restrict__ bias,
                       float* __restrict__ sK, float* __restrict__ sV) {
    const unsigned idx = blockIdx.x * 256u + threadIdx.x;   // < 196608
    const unsigned row = idx / 768u;                        // 0..255
    const unsigned c4  = idx % 768u;
    const unsigned col = c4 * 4;
    const size_t o = (size_t)row * 3072 + col;

    float4 s = *(const float4*)&g_part[o];
    #pragma unroll
    for (int kz = 1; kz < KSPLIT; kz++) {
        float4 p = *(const float4*)&g_part[(size_t)kz * (M_ROWS * 3072) + o];
        s.x += p.x; s.y += p.y; s.z += p.z; s.w += p.w;
    }
    float4 bb = *(const float4*)&bias[col];
    s.x += bb.x; s.y += bb.y; s.z += bb.z; s.w += bb.w;
    *(float4*)&g_qkv[o] = s;

    if (col >= 1024) {
        const unsigned tt = (col >= 2048) ? (col - 2048) : (col - 1024);
        float* dst = (col >= 2048) ? sV : sK;
        const unsigned hh = tt >> 6, dd = tt & 63u;
        const unsigned bq = row >> 4, sq = row & 15u;
        const size_t doff = ((size_t)(bq * 16 + hh) * L_TOT + PAST + sq) * 64 + dd;
        *(float4*)&dst[doff] = s;
    }
}

// ---------------------------------------------------------------------------
// Y reduce: sum 4 split-K partials + bias -> out_y. 256 blocks x 256 thr.
// ---------------------------------------------------------------------------
__global__ __launch_bounds__(256)
void y_reduce_kernel(const float* __restrict__ bias, float* __restrict__ Y) {
    const unsigned idx = blockIdx.x * 256u + threadIdx.x;   // < 65536
    const unsigned row = idx >> 8;                          // /256 float4 per row
    const unsigned col = (idx & 255u) * 4;
    const size_t o = (size_t)row * 1024 + col;

    float4 s = *(const float4*)&g_part[o];
    #pragma unroll
    for (int kz = 1; kz < KSPLIT; kz++) {
        float4 p = *(const float4*)&g_part[(size_t)kz * (M_ROWS * 1024) + o];
        s.x += p.x; s.y += p.y; s.z += p.z; s.w += p.w;
    }
    float4 bb = *(const float4*)&bias[col];
    s.x += bb.x; s.y += bb.y; s.z += bb.z; s.w += bb.w;
    *(float4*)&Y[o] = s;
}

// ---------------------------------------------------------------------------
// Fused attention + cache copy-out, split-KV x8, 3xTF32 tensor cores,
// cp.async double-buffered 32-row tiles, warp-specialized copy-out.
// (unchanged from round 11)
// ---------------------------------------------------------------------------
__global__ __launch_bounds__(256)
void attn_split_kernel(const float* __restrict__ cache_k,
                       const float* __restrict__ cache_v,
                       float* __restrict__ out_k,
                       float* __restrict__ out_v) {
    __shared__ unsigned qh[16][68];
    __shared__ unsigned ql[16][68];
    __shared__ __align__(16) float kt[2][TILE][68];
    __shared__ __align__(16) float vt[2][TILE][68];
    __shared__ float ptT[16][36];
    __shared__ float m_run[16], l_run[16], fac_s[16];

    const int tid   = threadIdx.x;
    const int bh    = blockIdx.x >> 3;
    const int split = blockIdx.x & 7;
    const int b = bh >> 4, h = bh & 15;

    const int w   = tid >> 5;
    const int L   = tid & 31;
    const int lr4 = L >> 2;
    const int lc4 = L & 3;

    {
        const int q = tid >> 4, c4 = tid & 15;
        float4 qv = *(const float4*)&g_qkv[(size_t)(b * 16 + q) * 3072 + h * 64 + c4 * 4];
        qv.x *= 0.125f; qv.y *= 0.125f; qv.z *= 0.125f; qv.w *= 0.125f;
        unsigned hi, lo;
        tf_split(qv.x, hi, lo); qh[q][c4 * 4 + 0] = hi; ql[q][c4 * 4 + 0] = lo;
        tf_split(qv.y, hi, lo); qh[q][c4 * 4 + 1] = hi; ql[q][c4 * 4 + 1] = lo;
        tf_split(qv.z, hi, lo); qh[q][c4 * 4 + 2] = hi; ql[q][c4 * 4 + 2] = lo;
        tf_split(qv.w, hi, lo); qh[q][c4 * 4 + 3] = hi; ql[q][c4 * 4 + 3] = lo;
    }
    if (tid < 16) { m_run[tid] = -1e30f; l_run[tid] = 0.0f; }

    const int chunk0 = split * 512;
    const int nrows  = (split == 7) ? 528 : 512;
    const int ntiles = (split == 7) ? 17 : 16;
    const size_t cbase = (size_t)bh * (PAST * 64);
    const size_t obase = (size_t)bh * (L_TOT * 64);

    const int sr = tid >> 4;
    const int sc = tid & 15;

    const int pq = tid >> 4;
    const int dc = tid & 15;

    float oc0 = 0.f, oc1 = 0.f, oc2 = 0.f, oc3 = 0.f;

    auto stage = [&](int t, int bb) {
        const int l0 = chunk0 + t * TILE;
        const int rows = min(TILE, chunk0 + nrows - l0);
        #pragma unroll
        for (int i = 0; i < 2; i++) {
            const int r = sr + i * 16;
            if (r < rows) {
                const int gl = l0 + r;
                const size_t off = (size_t)gl * 64 + sc * 4;
                const float* ksrc = (gl < PAST) ? (cache_k + cbase + off)
                                                : (out_k + obase + off);
                const float* vsrc = (gl < PAST) ? (cache_v + cbase + off)
                                                : (out_v + obase + off);
                CP_ASYNC16(smem_u32(&kt[bb][r][sc * 4]), ksrc);
                CP_ASYNC16(smem_u32(&vt[bb][r][sc * 4]), vsrc);
            }
        }
    };

    stage(0, 0);
    CP_COMMIT();

    for (int t = 0; t < ntiles; t++) {
        const int bb   = t & 1;
        const int l0   = chunk0 + t * TILE;
        const int rows = min(TILE, chunk0 + nrows - l0);

        __syncthreads();

        if (t + 1 < ntiles) {
            stage(t + 1, bb ^ 1);
            CP_COMMIT();
            CP_WAIT1();
        } else {
            CP_WAIT0();
        }
        __syncthreads();

        if (w < 4) {
            float c0 = 0.f, c1 = 0.f, c2 = 0.f, c3 = 0.f;
            #pragma unroll
            for (int ks = 0; ks < 8; ks++) {
                const int k0 = ks * 8;
                unsigned ah0 = qh[lr4    ][k0 + lc4];
                unsigned ah1 = qh[lr4 + 8][k0 + lc4];
                unsigned ah2 = qh[lr4    ][k0 + 4 + lc4];
                unsigned ah3 = qh[lr4 + 8][k0 + 4 + lc4];
                unsigned al0 = ql[lr4    ][k0 + lc4];
                unsigned al1 = ql[lr4 + 8][k0 + lc4];
                unsigned al2 = ql[lr4    ][k0 + 4 + lc4];
                unsigned al3 = ql[lr4 + 8][k0 + 4 + lc4];
                float b0f = kt[bb][w * 8 + lr4][k0 + lc4];
                float b1f = kt[bb][w * 8 + lr4][k0 + 4 + lc4];
                unsigned bh0, bl0, bh1, bl1;
                tf_split(b0f, bh0, bl0);
                tf_split(b1f, bh1, bl1);
                mma_tf32(c0, c1, c2, c3, ah0, ah1, ah2, ah3, bh0, bh1);
                mma_tf32(c0, c1, c2, c3, ah0, ah1, ah2, ah3, bl0, bl1);
                mma_tf32(c0, c1, c2, c3, al0, al1, al2, al3, bh0, bh1);
            }
            const int n = w * 8 + lc4 * 2;
            ptT[lr4    ][n    ] = (n     < rows) ? c0 : -1e30f;
            ptT[lr4    ][n + 1] = (n + 1 < rows) ? c1 : -1e30f;
            ptT[lr4 + 8][n    ] = (n     < rows) ? c2 : -1e30f;
            ptT[lr4 + 8][n + 1] = (n + 1 < rows) ? c3 : -1e30f;
        } else {
            const int wtid = tid - 128;
            const int cr = wtid >> 4;
            const int cc = wtid & 15;
            #pragma unroll
            for (int j = 0; j < 4; j++) {
                const int r = cr + j * 8;
                const int gl = l0 + r;
                if (r < rows && gl < PAST) {
                    const size_t off = (size_t)gl * 64 + cc * 4;
                    *(float4*)&out_k[obase + off] = *(const float4*)&kt[bb][r][cc * 4];
                    *(float4*)&out_v[obase + off] = *(const float4*)&vt[bb][r][cc * 4];
                }
            }
        }
        __syncthreads();

        {
            float2 p = *(const float2*)&ptT[pq][dc * 2];
            float mt = fmaxf(p.x, p.y);
            #pragma unroll
            for (int s = 8; s >= 1; s >>= 1)
                mt = fmaxf(mt, __shfl_xor_sync(0xffffffffu, mt, s, 16));
            const float mo = m_run[pq];
            const float mn = fmaxf(mo, mt);
            const float fc = __expf(mo - mn);
            p.x = __expf(p.x - mn);
            p.y = __expf(p.y - mn);
            *(float2*)&ptT[pq][dc * 2] = p;
            float ss = p.x + p.y;
            #pragma unroll
            for (int s = 8; s >= 1; s >>= 1)
                ss += __shfl_xor_sync(0xffffffffu, ss, s, 16);
            if (dc == 0) {
                m_run[pq] = mn;
                fac_s[pq] = fc;
                l_run[pq] = l_run[pq] * fc + ss;
            }
        }
        __syncthreads();

        {
            const float f0 = fac_s[lr4];
            const float f1 = fac_s[lr4 + 8];
            oc0 *= f0; oc1 *= f0; oc2 *= f1; oc3 *= f1;

            #pragma unroll
            for (int ks = 0; ks < 4; ks++) {
                const int k0 = ks * 8;
                float af0 = ptT[lr4    ][k0 + lc4];
                float af1 = ptT[lr4 + 8][k0 + lc4];
                float af2 = ptT[lr4    ][k0 + 4 + lc4];
                float af3 = ptT[lr4 + 8][k0 + 4 + lc4];
                unsigned ah0, al0, ah1, al1, ah2, al2, ah3, al3;
                tf_split(af0, ah0, al0);
                tf_split(af1, ah1, al1);
                tf_split(af2, ah2, al2);
                tf_split(af3, ah3, al3);
                float b0f = vt[bb][k0 + lc4    ][w * 8 + lr4];
                float b1f = vt[bb][k0 + 4 + lc4][w * 8 + lr4];
                unsigned bh0, bl0, bh1, bl1;
                tf_split(b0f, bh0, bl0);
                tf_split(b1f, bh1, bl1);
                mma_tf32(oc0, oc1, oc2, oc3, ah0, ah1, ah2, ah3, bh0, bh1);
                mma_tf32(oc0, oc1, oc2, oc3, ah0, ah1, ah2, ah3, bl0, bl1);
                mma_tf32(oc0, oc1, oc2, oc3, al0, al1, al2, al3, bh0, bh1);
            }
        }
    }

    {
        const size_t pbase = (size_t)blockIdx.x * 1024;
        const int d = w * 8 + lc4 * 2;
        *(float2*)&g_po[pbase + lr4       * 64 + d] = make_float2(oc0, oc1);
        *(float2*)&g_po[pbase + (lr4 + 8) * 64 + d] = make_float2(oc2, oc3);
    }
    if (tid < 16) {
        g_pm[blockIdx.x * 16 + tid] = m_run[tid];
        g_pl[blockIdx.x * 16 + tid] = l_run[tid];
    }
}

// ---------------------------------------------------------------------------
// Combine split partials -> g_obuf [B,S,H*hd]
// ---------------------------------------------------------------------------
__global__ __launch_bounds__(256)
void attn_reduce_kernel() {
    const int bh = blockIdx.x;
    const int tid = threadIdx.x;
    const int pq = tid >> 4, dc = tid & 15;
    const int base = bh * NSPLIT;

    float mm = -1e30f;
    #pragma unroll
    for (int s = 0; s < NSPLIT; s++)
        mm = fmaxf(mm, g_pm[(base + s) * 16 + pq]);

    float4 acc = make_float4(0.f, 0.f, 0.f, 0.f);
    float l = 0.f;
    #pragma unroll
    for (int s = 0; s < NSPLIT; s++) {
        float w = __expf(g_pm[(base + s) * 16 + pq] - mm);
        float4 o = *(const float4*)&g_po[(size_t)(base + s) * 1024 + pq * 64 + dc * 4];
        acc.x += w * o.x; acc.y += w * o.y;
        acc.z += w * o.z; acc.w += w * o.w;
        l += w * g_pl[(base + s) * 16 + pq];
    }
    float inv = 1.0f / l;
    const int b = bh >> 4, h = bh & 15;
    float4 r = make_float4(acc.x * inv, acc.y * inv, acc.z * inv, acc.w * inv);
    *(float4*)&g_obuf[(size_t)(b * 16 + pq) * D_MODEL + h * 64 + dc * 4] = r;
}

// ---------------------------------------------------------------------------
extern "C" void kernel_launch(void* const* d_in, const int* in_sizes, int n_in,
                              void* d_out, int out_size) {
    const float* x       = (const float*)d_in[0];
    const float* cache_k = (const float*)d_in[1];
    const float* cache_v = (const float*)d_in[2];
    const float* qkv_w   = (const float*)d_in[3];
    const float* qkv_b   = (const float*)d_in[4];
    const float* out_w   = (const float*)d_in[5];
    const float* out_b   = (const float*)d_in[6];

    float* out   = (float*)d_out;
    float* out_y = out + OUT_Y_OFF;
    float* out_k = out + OUT_K_OFF;
    float* out_v = out + OUT_V_OFF;

    float *obuf_p = nullptr, *part_p = nullptr;
    cudaGetSymbolAddress((void**)&obuf_p, g_obuf);
    cudaGetSymbolAddress((void**)&part_p, g_part);

    // 1) QKV projection, split-K x4 -> partials
    gemm_tf32_split_kernel<<<dim3(3072 / 64, M_ROWS / 64, KSPLIT), 256>>>(
        x, qkv_w, part_p, 3072, D_MODEL);

    // 2) Reduce partials + bias -> g_qkv; scatter new K/V rows
    qkv_reduce_kernel<<<768, 256>>>(qkv_b, out_k, out_v);

    // 3) Fused attention + cache copy-out (split-KV x8, TC + cp.async)
    attn_split_kernel<<<B_SZ * H_SZ * NSPLIT, 256>>>(cache_k, cache_v, out_k, out_v);

    // 4) Combine splits -> g_obuf
    attn_reduce_kernel<<<B_SZ * H_SZ, 256>>>();

    // 5) Output projection, split-K x4 -> partials
    gemm_tf32_split_kernel<<<dim3(D_MODEL / 64, M_ROWS / 64, KSPLIT), 256>>>(
        obuf_p, out_w, part_p, D_MODEL, D_MODEL);

    // 6) Reduce partials + bias -> y
    y_reduce_kernel<<<256, 256>>>(out_b, out_y);
}

// round 13
// speedup vs baseline: 1.4242x; 1.0100x over previous
#include <cuda_runtime.h>
#include <cuda_bf16.h>
#include <cstddef>

// Problem constants
#define B_SZ    16
#define S_SZ    16
#define H_SZ    16
#define HD      64
#define D_MODEL 1024
#define PAST    4096
#define L_TOT   4112
#define M_ROWS  256
#define NSPLIT  16
#define TILE    32
#define KSPLIT  4

// Output layout offsets (floats): y | k | v
#define OUT_Y_OFF 0
#define OUT_K_OFF (256*1024)
#define OUT_V_OFF (OUT_K_OFF + 256*4112*64)

// cp.async helpers
__device__ __forceinline__ unsigned smem_u32(const void* p) {
    return (unsigned)__cvta_generic_to_shared(p);
}
#define CP_ASYNC16(dst_u32, src_ptr) \
    asm volatile("cp.async.cg.shared.global [%0], [%1], 16;\n" \
                 :: "r"(dst_u32), "l"(src_ptr))
#define CP_COMMIT() asm volatile("cp.async.commit_group;\n" ::)
#define CP_WAIT3()  asm volatile("cp.async.wait_group 3;\n" ::)
#define CP_WAIT1()  asm volatile("cp.async.wait_group 1;\n" ::)
#define CP_WAIT0()  asm volatile("cp.async.wait_group 0;\n" ::)

// Scratch (device globals; no allocations allowed)
__device__ float g_qkv [M_ROWS * 3 * D_MODEL];            // [256, 3072]
__device__ float g_obuf[M_ROWS * D_MODEL];                // [256, 1024]
__device__ float g_part[KSPLIT * M_ROWS * 3 * D_MODEL];   // split-K partials
__device__ float g_po  [256 * NSPLIT * 16 * 64];
__device__ float g_pm  [256 * NSPLIT * 16];
__device__ float g_pl  [256 * NSPLIT * 16];

// ---- tf32 helpers --------------------------------------------------------
__device__ __forceinline__ unsigned f2tf(float x) {
    unsigned r; asm("cvt.rna.tf32.f32 %0, %1;" : "=r"(r) : "f"(x)); return r;
}
__device__ __forceinline__ void tf_split(float x, unsigned& hi, unsigned& lo) {
    hi = f2tf(x);
    lo = f2tf(x - __uint_as_float(hi));
}
__device__ __forceinline__ void mma_tf32(float& c0, float& c1, float& c2, float& c3,
                                         unsigned a0, unsigned a1, unsigned a2, unsigned a3,
                                         unsigned b0, unsigned b1) {
    asm volatile(
        "mma.sync.aligned.m16n8k8.row.col.f32.tf32.tf32.f32 "
        "{%0,%1,%2,%3}, {%4,%5,%6,%7}, {%8,%9}, {%0,%1,%2,%3};\n"
        : "+f"(c0), "+f"(c1), "+f"(c2), "+f"(c3)
        : "r"(a0), "r"(a1), "r"(a2), "r"(a3), "r"(b0), "r"(b1));
}

// ---------------------------------------------------------------------------
// Split-K tensor-core GEMM (3xTF32), cp.async 4-stage pipeline.
// If Yred == nullptr: partials -> P[(kz*M + row)*N + n].
// Else: RED (atomicAdd) into Yred; kz==0 block adds bias. Yred must be
// zeroed earlier in the stream.
// ---------------------------------------------------------------------------
__global__ __launch_bounds__(256)
void gemm_tf32_split_kernel(const float* __restrict__ A, const float* __restrict__ W,
                            float* __restrict__ P, int N, int K,
                            float* __restrict__ Yred, const float* __restrict__ bias) {
    __shared__ __align__(16) float As[4][64][20];
    __shared__ __align__(16) float Bs[4][64][20];

    const int tid = threadIdx.x;
    const int w   = tid >> 5;
    const int L   = tid & 31;
    const int lr4 = L >> 2;
    const int lc4 = L & 3;
    const int mf  = w >> 1;
    const int nh  = w & 1;

    const int m0 = blockIdx.y * 64;
    const int n0 = blockIdx.x * 64;
    const int kz = blockIdx.z;
    const int kbase = kz * (K / KSPLIT);

    const int srow = tid >> 2;
    const int sch  = (tid & 3) * 4;

    float acc[4][4];
    #pragma unroll
    for (int i = 0; i < 4; i++)
        #pragma unroll
        for (int j = 0; j < 4; j++) acc[i][j] = 0.f;

    const int mbase = mf * 16;
    const int nbase = nh * 32;
    const int niter = (K / KSPLIT) / 16;   // 16

    #pragma unroll
    for (int p = 0; p < 3; p++) {
        CP_ASYNC16(smem_u32(&As[p][srow][sch]),
                   &A[(size_t)(m0 + srow) * K + kbase + p * 16 + sch]);
        CP_ASYNC16(smem_u32(&Bs[p][srow][sch]),
                   &W[(size_t)(n0 + srow) * K + kbase + p * 16 + sch]);
        CP_COMMIT();
    }

    for (int t = 0; t < niter; t++) {
        const int bb = t & 3;

        if (t + 3 < niter) {
            const int k1 = kbase + (t + 3) * 16;
            const int pb = (t + 3) & 3;
            CP_ASYNC16(smem_u32(&As[pb][srow][sch]),
                       &A[(size_t)(m0 + srow) * K + k1 + sch]);
            CP_ASYNC16(smem_u32(&Bs[pb][srow][sch]),
                       &W[(size_t)(n0 + srow) * K + k1 + sch]);
        }
        CP_COMMIT();
        CP_WAIT3();
        __syncthreads();

        #pragma unroll
        for (int ks = 0; ks < 2; ks++) {
            const int kk = ks * 8;
            float af0 = As[bb][mbase + lr4    ][kk + lc4];
            float af1 = As[bb][mbase + lr4 + 8][kk + lc4];
            float af2 = As[bb][mbase + lr4    ][kk + 4 + lc4];
            float af3 = As[bb][mbase + lr4 + 8][kk + 4 + lc4];
            unsigned ah0, al0, ah1, al1, ah2, al2, ah3, al3;
            tf_split(af0, ah0, al0);
            tf_split(af1, ah1, al1);
            tf_split(af2, ah2, al2);
            tf_split(af3, ah3, al3);

            #pragma unroll
            for (int nf = 0; nf < 4; nf++) {
                const int nn = nbase + nf * 8 + lr4;
                float bf0 = Bs[bb][nn][kk + lc4];
                float bf1 = Bs[bb][nn][kk + 4 + lc4];
                unsigned bh0, bl0, bh1, bl1;
                tf_split(bf0, bh0, bl0);
                tf_split(bf1, bh1, bl1);
                mma_tf32(acc[nf][0], acc[nf][1], acc[nf][2], acc[nf][3],
                         ah0, ah1, ah2, ah3, bh0, bh1);
                mma_tf32(acc[nf][0], acc[nf][1], acc[nf][2], acc[nf][3],
                         ah0, ah1, ah2, ah3, bl0, bl1);
                mma_tf32(acc[nf][0], acc[nf][1], acc[nf][2], acc[nf][3],
                         al0, al1, al2, al3, bh0, bh1);
            }
        }
        __syncthreads();
    }

    const int row0 = m0 + mbase + lr4;
    if (Yred == nullptr) {
        const size_t pb0 = (size_t)kz * M_ROWS;
        #pragma unroll
        for (int nf = 0; nf < 4; nf++) {
            const int n = n0 + nbase + nf * 8 + lc4 * 2;
            *(float2*)&P[(pb0 + row0) * N + n]     = make_float2(acc[nf][0], acc[nf][1]);
            *(float2*)&P[(pb0 + row0 + 8) * N + n] = make_float2(acc[nf][2], acc[nf][3]);
        }
    } else {
        #pragma unroll
        for (int nf = 0; nf < 4; nf++) {
            const int n = n0 + nbase + nf * 8 + lc4 * 2;
            float v00 = acc[nf][0], v01 = acc[nf][1];
            float v10 = acc[nf][2], v11 = acc[nf][3];
            if (kz == 0) {
                float2 bb2 = *(const float2*)&bias[n];
                v00 += bb2.x; v01 += bb2.y;
                v10 += bb2.x; v11 += bb2.y;
            }
            atomicAdd(&Yred[(size_t)row0 * N + n],       v00);
            atomicAdd(&Yred[(size_t)row0 * N + n + 1],   v01);
            atomicAdd(&Yred[(size_t)(row0 + 8) * N + n],     v10);
            atomicAdd(&Yred[(size_t)(row0 + 8) * N + n + 1], v11);
        }
    }
}

// ---------------------------------------------------------------------------
// QKV reduce: sum 4 split-K partials + bias -> g_qkv; scatter new K/V rows
// into out_k/out_v tails; spare threads zero out_y for the RED epilogue.
// ---------------------------------------------------------------------------
__global__ __launch_bounds__(256)
void qkv_reduce_kernel(const float* __restrict__ bias,
                       float* __restrict__ sK, float* __restrict__ sV,
                       float* __restrict__ Y) {
    const unsigned idx = blockIdx.x * 256u + threadIdx.x;   // < 196608

    // zero out_y (262144 floats = 65536 float4)
    if (idx < 65536u)
        *(float4*)&Y[idx * 4] = make_float4(0.f, 0.f, 0.f, 0.f);

    const unsigned row = idx / 768u;                        // 0..255
    const unsigned c4  = idx % 768u;
    const unsigned col = c4 * 4;
    const size_t o = (size_t)row * 3072 + col;

    float4 s = *(const float4*)&g_part[o];
    #pragma unroll
    for (int kz = 1; kz < KSPLIT; kz++) {
        float4 p = *(const float4*)&g_part[(size_t)kz * (M_ROWS * 3072) + o];
        s.x += p.x; s.y += p.y; s.z += p.z; s.w += p.w;
    }
    float4 bb = *(const float4*)&bias[col];
    s.x += bb.x; s.y += bb.y; s.z += bb.z; s.w += bb.w;
    *(float4*)&g_qkv[o] = s;

    if (col >= 1024) {
        const unsigned tt = (col >= 2048) ? (col - 2048) : (col - 1024);
        float* dst = (col >= 2048) ? sV : sK;
        const unsigned hh = tt >> 6, dd = tt & 63u;
        const unsigned bq = row >> 4, sq = row & 15u;
        const size_t doff = ((size_t)(bq * 16 + hh) * L_TOT + PAST + sq) * 64 + dd;
        *(float4*)&dst[doff] = s;
    }
}

// ---------------------------------------------------------------------------
// Fused attention + cache copy-out, split-KV x16, 3xTF32 tensor cores,
// cp.async double-buffered 32-row tiles, warp-specialized copy-out.
// ---------------------------------------------------------------------------
__global__ __launch_bounds__(256)
void attn_split_kernel(const float* __restrict__ cache_k,
                       const float* __restrict__ cache_v,
                       float* __restrict__ out_k,
                       float* __restrict__ out_v) {
    __shared__ unsigned qh[16][68];
    __shared__ unsigned ql[16][68];
    __shared__ __align__(16) float kt[2][TILE][68];
    __shared__ __align__(16) float vt[2][TILE][68];
    __shared__ float ptT[16][36];
    __shared__ float m_run[16], l_run[16], fac_s[16];

    const int tid   = threadIdx.x;
    const int bh    = blockIdx.x >> 4;
    const int split = blockIdx.x & 15;
    const int b = bh >> 4, h = bh & 15;

    const int w   = tid >> 5;
    const int L   = tid & 31;
    const int lr4 = L >> 2;
    const int lc4 = L & 3;

    {
        const int q = tid >> 4, c4 = tid & 15;
        float4 qv = *(const float4*)&g_qkv[(size_t)(b * 16 + q) * 3072 + h * 64 + c4 * 4];
        qv.x *= 0.125f; qv.y *= 0.125f; qv.z *= 0.125f; qv.w *= 0.125f;
        unsigned hi, lo;
        tf_split(qv.x, hi, lo); qh[q][c4 * 4 + 0] = hi; ql[q][c4 * 4 + 0] = lo;
        tf_split(qv.y, hi, lo); qh[q][c4 * 4 + 1] = hi; ql[q][c4 * 4 + 1] = lo;
        tf_split(qv.z, hi, lo); qh[q][c4 * 4 + 2] = hi; ql[q][c4 * 4 + 2] = lo;
        tf_split(qv.w, hi, lo); qh[q][c4 * 4 + 3] = hi; ql[q][c4 * 4 + 3] = lo;
    }
    if (tid < 16) { m_run[tid] = -1e30f; l_run[tid] = 0.0f; }

    const int chunk0 = split * 256;
    const int nrows  = (split == 15) ? 272 : 256;
    const int ntiles = (split == 15) ? 9 : 8;
    const size_t cbase = (size_t)bh * (PAST * 64);
    const size_t obase = (size_t)bh * (L_TOT * 64);

    const int sr = tid >> 4;
    const int sc = tid & 15;

    const int pq = tid >> 4;
    const int dc = tid & 15;

    float oc0 = 0.f, oc1 = 0.f, oc2 = 0.f, oc3 = 0.f;

    auto stage = [&](int t, int bb) {
        const int l0 = chunk0 + t * TILE;
        const int rows = min(TILE, chunk0 + nrows - l0);
        #pragma unroll
        for (int i = 0; i < 2; i++) {
            const int r = sr + i * 16;
            if (r < rows) {
                const int gl = l0 + r;
                const size_t off = (size_t)gl * 64 + sc * 4;
                const float* ksrc = (gl < PAST) ? (cache_k + cbase + off)
                                                : (out_k + obase + off);
                const float* vsrc = (gl < PAST) ? (cache_v + cbase + off)
                                                : (out_v + obase + off);
                CP_ASYNC16(smem_u32(&kt[bb][r][sc * 4]), ksrc);
                CP_ASYNC16(smem_u32(&vt[bb][r][sc * 4]), vsrc);
            }
        }
    };

    stage(0, 0);
    CP_COMMIT();

    for (int t = 0; t < ntiles; t++) {
        const int bb   = t & 1;
        const int l0   = chunk0 + t * TILE;
        const int rows = min(TILE, chunk0 + nrows - l0);

        __syncthreads();

        if (t + 1 < ntiles) {
            stage(t + 1, bb ^ 1);
            CP_COMMIT();
            CP_WAIT1();
        } else {
            CP_WAIT0();
        }
        __syncthreads();

        if (w < 4) {
            float c0 = 0.f, c1 = 0.f, c2 = 0.f, c3 = 0.f;
            #pragma unroll
            for (int ks = 0; ks < 8; ks++) {
                const int k0 = ks * 8;
                unsigned ah0 = qh[lr4    ][k0 + lc4];
                unsigned ah1 = qh[lr4 + 8][k0 + lc4];
                unsigned ah2 = qh[lr4    ][k0 + 4 + lc4];
                unsigned ah3 = qh[lr4 + 8][k0 + 4 + lc4];
                unsigned al0 = ql[lr4    ][k0 + lc4];
                unsigned al1 = ql[lr4 + 8][k0 + lc4];
                unsigned al2 = ql[lr4    ][k0 + 4 + lc4];
                unsigned al3 = ql[lr4 + 8][k0 + 4 + lc4];
                float b0f = kt[bb][w * 8 + lr4][k0 + lc4];
                float b1f = kt[bb][w * 8 + lr4][k0 + 4 + lc4];
                unsigned bh0, bl0, bh1, bl1;
                tf_split(b0f, bh0, bl0);
                tf_split(b1f, bh1, bl1);
                mma_tf32(c0, c1, c2, c3, ah0, ah1, ah2, ah3, bh0, bh1);
                mma_tf32(c0, c1, c2, c3, ah0, ah1, ah2, ah3, bl0, bl1);
                mma_tf32(c0, c1, c2, c3, al0, al1, al2, al3, bh0, bh1);
            }
            const int n = w * 8 + lc4 * 2;
            ptT[lr4    ][n    ] = (n     < rows) ? c0 : -1e30f;
            ptT[lr4    ][n + 1] = (n + 1 < rows) ? c1 : -1e30f;
            ptT[lr4 + 8][n    ] = (n     < rows) ? c2 : -1e30f;
            ptT[lr4 + 8][n + 1] = (n + 1 < rows) ? c3 : -1e30f;
        } else {
            const int wtid = tid - 128;
            const int cr = wtid >> 4;
            const int cc = wtid & 15;
            #pragma unroll
            for (int j = 0; j < 4; j++) {
                const int r = cr + j * 8;
                const int gl = l0 + r;
                if (r < rows && gl < PAST) {
                    const size_t off = (size_t)gl * 64 + cc * 4;
                    *(float4*)&out_k[obase + off] = *(const float4*)&kt[bb][r][cc * 4];
                    *(float4*)&out_v[obase + off] = *(const float4*)&vt[bb][r][cc * 4];
                }
            }
        }
        __syncthreads();

        {
            float2 p = *(const float2*)&ptT[pq][dc * 2];
            float mt = fmaxf(p.x, p.y);
            #pragma unroll
            for (int s = 8; s >= 1; s >>= 1)
                mt = fmaxf(mt, __shfl_xor_sync(0xffffffffu, mt, s, 16));
            const float mo = m_run[pq];
            const float mn = fmaxf(mo, mt);
            const float fc = __expf(mo - mn);
            p.x = __expf(p.x - mn);
            p.y = __expf(p.y - mn);
            *(float2*)&ptT[pq][dc * 2] = p;
            float ss = p.x + p.y;
            #pragma unroll
            for (int s = 8; s >= 1; s >>= 1)
                ss += __shfl_xor_sync(0xffffffffu, ss, s, 16);
            if (dc == 0) {
                m_run[pq] = mn;
                fac_s[pq] = fc;
                l_run[pq] = l_run[pq] * fc + ss;
            }
        }
        __syncthreads();

        {
            const float f0 = fac_s[lr4];
            const float f1 = fac_s[lr4 + 8];
            oc0 *= f0; oc1 *= f0; oc2 *= f1; oc3 *= f1;

            #pragma unroll
            for (int ks = 0; ks < 4; ks++) {
                const int k0 = ks * 8;
                float af0 = ptT[lr4    ][k0 + lc4];
                float af1 = ptT[lr4 + 8][k0 + lc4];
                float af2 = ptT[lr4    ][k0 + 4 + lc4];
                float af3 = ptT[lr4 + 8][k0 + 4 + lc4];
                unsigned ah0, al0, ah1, al1, ah2, al2, ah3, al3;
                tf_split(af0, ah0, al0);
                tf_split(af1, ah1, al1);
                tf_split(af2, ah2, al2);
                tf_split(af3, ah3, al3);
                float b0f = vt[bb][k0 + lc4    ][w * 8 + lr4];
                float b1f = vt[bb][k0 + 4 + lc4][w * 8 + lr4];
                unsigned bh0, bl0, bh1, bl1;
                tf_split(b0f, bh0, bl0);
                tf_split(b1f, bh1, bl1);
                mma_tf32(oc0, oc1, oc2, oc3, ah0, ah1, ah2, ah3, bh0, bh1);
                mma_tf32(oc0, oc1, oc2, oc3, ah0, ah1, ah2, ah3, bl0, bl1);
                mma_tf32(oc0, oc1, oc2, oc3, al0, al1, al2, al3, bh0, bh1);
            }
        }
    }

    {
        const size_t pbase = (size_t)blockIdx.x * 1024;
        const int d = w * 8 + lc4 * 2;
        *(float2*)&g_po[pbase + lr4       * 64 + d] = make_float2(oc0, oc1);
        *(float2*)&g_po[pbase + (lr4 + 8) * 64 + d] = make_float2(oc2, oc3);
    }
    if (tid < 16) {
        g_pm[blockIdx.x * 16 + tid] = m_run[tid];
        g_pl[blockIdx.x * 16 + tid] = l_run[tid];
    }
}

// ---------------------------------------------------------------------------
// Combine split partials -> g_obuf [B,S,H*hd]
// ---------------------------------------------------------------------------
__global__ __launch_bounds__(256)
void attn_reduce_kernel() {
    const int bh = blockIdx.x;
    const int tid = threadIdx.x;
    const int pq = tid >> 4, dc = tid & 15;
    const int base = bh * NSPLIT;

    float mm = -1e30f;
    #pragma unroll
    for (int s = 0; s < NSPLIT; s++)
        mm = fmaxf(mm, g_pm[(base + s) * 16 + pq]);

    float4 acc = make_float4(0.f, 0.f, 0.f, 0.f);
    float l = 0.f;
    #pragma unroll
    for (int s = 0; s < NSPLIT; s++) {
        float w = __expf(g_pm[(base + s) * 16 + pq] - mm);
        float4 o = *(const float4*)&g_po[(size_t)(base + s) * 1024 + pq * 64 + dc * 4];
        acc.x += w * o.x; acc.y += w * o.y;
        acc.z += w * o.z; acc.w += w * o.w;
        l += w * g_pl[(base + s) * 16 + pq];
    }
    float inv = 1.0f / l;
    const int b = bh >> 4, h = bh & 15;
    float4 r = make_float4(acc.x * inv, acc.y * inv, acc.z * inv, acc.w * inv);
    *(float4*)&g_obuf[(size_t)(b * 16 + pq) * D_MODEL + h * 64 + dc * 4] = r;
}

// ---------------------------------------------------------------------------
extern "C" void kernel_launch(void* const* d_in, const int* in_sizes, int n_in,
                              void* d_out, int out_size) {
    const float* x       = (const float*)d_in[0];
    const float* cache_k = (const float*)d_in[1];
    const float* cache_v = (const float*)d_in[2];
    const float* qkv_w   = (const float*)d_in[3];
    const float* qkv_b   = (const float*)d_in[4];
    const float* out_w   = (const float*)d_in[5];
    const float* out_b   = (const float*)d_in[6];

    float* out   = (float*)d_out;
    float* out_y = out + OUT_Y_OFF;
    float* out_k = out + OUT_K_OFF;
    float* out_v = out + OUT_V_OFF;

    float *obuf_p = nullptr, *part_p = nullptr;
    cudaGetSymbolAddress((void**)&obuf_p, g_obuf);
    cudaGetSymbolAddress((void**)&part_p, g_part);

    // 1) QKV projection, split-K x4 -> partials
    gemm_tf32_split_kernel<<<dim3(3072 / 64, M_ROWS / 64, KSPLIT), 256>>>(
        x, qkv_w, part_p, 3072, D_MODEL, nullptr, nullptr);

    // 2) Reduce partials + bias -> g_qkv; scatter new K/V; zero out_y
    qkv_reduce_kernel<<<768, 256>>>(qkv_b, out_k, out_v, out_y);

    // 3) Fused attention + cache copy-out (split-KV x16, TC + cp.async)
    attn_split_kernel<<<B_SZ * H_SZ * NSPLIT, 256>>>(cache_k, cache_v, out_k, out_v);

    // 4) Combine splits -> g_obuf
    attn_reduce_kernel<<<B_SZ * H_SZ, 256>>>();

    // 5) Output projection, split-K x4, RED directly into out_y (+bias)
    gemm_tf32_split_kernel<<<dim3(D_MODEL / 64, M_ROWS / 64, KSPLIT), 256>>>(
        obuf_p, out_w, nullptr, D_MODEL, D_MODEL, out_y, out_b);
}